// round 8
// baseline (speedup 1.0000x reference)
#include <cuda_runtime.h>
#include <cuda_bf16.h>
#include <cuda_fp16.h>
#include <cstdint>

#define N_NODES 4096
#define IN_F 512
#define OUT_F 64
#define HEADS 8
#define ALPHA 0.2f

#define RT 128                 // rows per CTA (wh kernel)
#define KC 32                  // k per chunk (wh kernel)
#define NCH_W (IN_F / KC)      // 16 chunks (wh)
#define ASTR 40                // padded bf16 row stride (80 B) (wh kernel)
#define BSTR 40

// ---- wh dynamic smem offsets ----
#define WH_A(buf, prec) ((buf) * 20480 + (prec) * 10240)
#define WH_B(buf, prec) (40960 + (buf) * 10240 + (prec) * 5120)
#define WH_SMEM 61440

// ---- gat (fp16, 128x64 tile, KC2=64) ----
#define GAT_RT 128
#define KC2 64
#define NCH2 (N_NODES / KC2)   // 64 chunks
#define AST2 72                // fp16 stride (144 B)
#define GA_A(buf) ((buf) * 18432)           // [128][72] fp16
#define GA_B(buf) (36864 + (buf) * 9216)    // [64][72] fp16
#define GA_DSH 55296                        // [128][8] float
#define GA_SMEM 59392

// ---------------- scratch (device globals; no allocation) ----------------
__device__ __align__(16) float g_Wh[HEADS * N_NODES * OUT_F];          // 8 MB [h][n][o]
__device__ float g_f1[HEADS * N_NODES];
__device__ float g_f2[HEADS * N_NODES];
__device__ float g_P1[HEADS * N_NODES];   // exp(f1 - M)  (shifted)
__device__ float g_P2[HEADS * N_NODES];   // exp(f2)
__device__ float g_Q1[HEADS * N_NODES];   // exp(a*f1 - M)
__device__ float g_Q2[HEADS * N_NODES];   // exp(a*f2)
__device__ float g_mx[HEADS];             // per-head max f2
__device__ unsigned g_adjbits[N_NODES * (N_NODES / 32)];               // 2 MB
__device__ __align__(16) __half g_WhT_h16[HEADS * OUT_F * N_NODES];    // 4 MB [h][o][m]
__device__ __align__(16) __nv_bfloat16 g_x_hi[N_NODES * IN_F];         // 4 MB [n][k]
__device__ __align__(16) __nv_bfloat16 g_x_lo[N_NODES * IN_F];
__device__ __align__(16) __nv_bfloat16 g_WT_hi[HEADS * OUT_F * IN_F];  // 512 KB [h][o][k]
__device__ __align__(16) __nv_bfloat16 g_WT_lo[HEADS * OUT_F * IN_F];

// ---------------- helpers ----------------
__device__ __forceinline__ uint32_t smem_u32(const void* p) {
    uint32_t a;
    asm("{ .reg .u64 t; cvta.to.shared.u64 t, %1; cvt.u32.u64 %0, t; }" : "=r"(a) : "l"(p));
    return a;
}
__device__ __forceinline__ void cp16(uint32_t dst, const void* src) {
    asm volatile("cp.async.cg.shared.global [%0], [%1], 16;" :: "r"(dst), "l"(src) : "memory");
}
__device__ __forceinline__ void cp_commit() {
    asm volatile("cp.async.commit_group;" ::: "memory");
}
template <int N>
__device__ __forceinline__ void cp_wait() {
    asm volatile("cp.async.wait_group %0;" :: "n"(N) : "memory");
}
__device__ __forceinline__ void ldm4(uint32_t* r, uint32_t addr) {
    asm volatile("ldmatrix.sync.aligned.m8n8.x4.shared.b16 {%0,%1,%2,%3}, [%4];"
                 : "=r"(r[0]), "=r"(r[1]), "=r"(r[2]), "=r"(r[3]) : "r"(addr) : "memory");
}
__device__ __forceinline__ void mma_bf16(float* c, const uint32_t* a, uint32_t b0,
                                         uint32_t b1) {
    asm("mma.sync.aligned.m16n8k16.row.col.f32.bf16.bf16.f32 "
        "{%0,%1,%2,%3}, {%4,%5,%6,%7}, {%8,%9}, {%0,%1,%2,%3};"
        : "+f"(c[0]), "+f"(c[1]), "+f"(c[2]), "+f"(c[3])
        : "r"(a[0]), "r"(a[1]), "r"(a[2]), "r"(a[3]), "r"(b0), "r"(b1));
}
__device__ __forceinline__ void mma_f16(float* c, const uint32_t* a, uint32_t b0,
                                        uint32_t b1) {
    asm("mma.sync.aligned.m16n8k16.row.col.f32.f16.f16.f32 "
        "{%0,%1,%2,%3}, {%4,%5,%6,%7}, {%8,%9}, {%0,%1,%2,%3};"
        : "+f"(c[0]), "+f"(c[1]), "+f"(c[2]), "+f"(c[3])
        : "r"(a[0]), "r"(a[1]), "r"(a[2]), "r"(a[3]), "r"(b0), "r"(b1));
}
__device__ __forceinline__ void split_pair(float x, float y, unsigned& hi, unsigned& lo) {
    __nv_bfloat162 h2 = __float22bfloat162_rn(make_float2(x, y));
    float2 hf = __bfloat1622float2(h2);
    __nv_bfloat162 l2 = __float22bfloat162_rn(make_float2(x - hf.x, y - hf.y));
    hi = *reinterpret_cast<unsigned*>(&h2);
    lo = *reinterpret_cast<unsigned*>(&l2);
}

// ---------------- kernel: bit-pack adjacency ----------------
__global__ __launch_bounds__(256) void bitpack_kernel(const int* __restrict__ adj) {
    int t = blockIdx.x * blockDim.x + threadIdx.x;
    const int4* p = (const int4*)adj + (size_t)t * 8;
    unsigned w = 0;
#pragma unroll
    for (int i = 0; i < 8; i++) {
        int4 v = p[i];
        w |= (v.x > 0 ? 1u : 0u) << (4 * i);
        w |= (v.y > 0 ? 1u : 0u) << (4 * i + 1);
        w |= (v.z > 0 ? 1u : 0u) << (4 * i + 2);
        w |= (v.w > 0 ? 1u : 0u) << (4 * i + 3);
    }
    g_adjbits[t] = w;
}

// ---------------- kernel: split x into bf16 hi/lo ----------------
__global__ __launch_bounds__(256) void xsplit_kernel(const float* __restrict__ x) {
    int gid = blockIdx.x * blockDim.x + threadIdx.x;
    const float4* xp = (const float4*)x + gid * 2;
    float4 v0 = xp[0], v1 = xp[1];
    float f[8] = {v0.x, v0.y, v0.z, v0.w, v1.x, v1.y, v1.z, v1.w};
    unsigned hw[4], lw[4];
#pragma unroll
    for (int i = 0; i < 4; i++) split_pair(f[2 * i], f[2 * i + 1], hw[i], lw[i]);
    *(uint4*)(g_x_hi + (size_t)gid * 8) = make_uint4(hw[0], hw[1], hw[2], hw[3]);
    *(uint4*)(g_x_lo + (size_t)gid * 8) = make_uint4(lw[0], lw[1], lw[2], lw[3]);
}

// ---------------- kernel: transpose + split W -> WT[h][o][k] ----------------
__global__ __launch_bounds__(256) void wsplit_kernel(const float* __restrict__ W) {
    const int h = blockIdx.x;
    const int t = threadIdx.x;
#pragma unroll 4
    for (int i = 0; i < 128; i++) {
        int lin = i * 256 + t;
        int o = lin >> 9, k = lin & 511;
        float v = W[((size_t)h * IN_F + k) * OUT_F + o];
        __nv_bfloat16 hb = __float2bfloat16(v);
        __nv_bfloat16 lb = __float2bfloat16(v - __bfloat162float(hb));
        size_t d = ((size_t)h * OUT_F + o) * IN_F + k;
        g_WT_hi[d] = hb;
        g_WT_lo[d] = lb;
    }
}

// ---------------- kernel: Wh = x @ W via HMMA (3-term bf16 split) ----------------
__global__ __launch_bounds__(256, 2) void wh_mma_kernel() {
    extern __shared__ __align__(16) char sm[];
    const int t = threadIdx.x;
    const int wid = t >> 5, lane = t & 31;
    const int h = blockIdx.y;
    const int nbase = blockIdx.x * RT;

    const int a_p[4] = {(t * 4) >> 9, (t * 4 + 1) >> 9, (t * 4 + 2) >> 9, (t * 4 + 3) >> 9};
    int a_r[4], a_q[4];
    const __nv_bfloat16* a_src[4];
    uint32_t a_doff[4];
#pragma unroll
    for (int i = 0; i < 4; i++) {
        int idx = t * 4 + i;
        a_r[i] = (idx >> 2) & 127;
        a_q[i] = idx & 3;
        a_src[i] = (a_p[i] ? g_x_lo : g_x_hi) + (size_t)(nbase + a_r[i]) * IN_F + a_q[i] * 8;
        a_doff[i] = (uint32_t)(a_r[i] * (ASTR * 2) + a_q[i] * 16);
    }
    int b_p[2];
    const __nv_bfloat16* b_src[2];
    uint32_t b_doff[2];
#pragma unroll
    for (int i = 0; i < 2; i++) {
        int idx = t * 2 + i;
        b_p[i] = idx >> 8;
        int br = (idx >> 2) & 63, bq = idx & 3;
        b_src[i] = (b_p[i] ? g_WT_lo : g_WT_hi) + ((size_t)h * OUT_F + br) * IN_F + bq * 8;
        b_doff[i] = (uint32_t)(br * (BSTR * 2) + bq * 16);
    }
    const uint32_t smb = smem_u32(sm);

#pragma unroll
    for (int i = 0; i < 4; i++) cp16(smb + WH_A(0, a_p[i]) + a_doff[i], a_src[i]);
#pragma unroll
    for (int i = 0; i < 2; i++) cp16(smb + WH_B(0, b_p[i]) + b_doff[i], b_src[i]);
    cp_commit();

    float acc[8][4];
#pragma unroll
    for (int j = 0; j < 8; j++)
#pragma unroll
        for (int q = 0; q < 4; q++) acc[j][q] = 0.f;

    const uint32_t aRow = (16 * wid + (lane & 15)) * (ASTR * 2) + (lane >> 4) * 16;
    const uint32_t bRow = (lane & 7) * (BSTR * 2) + (lane >> 3) * 16;

    for (int c = 0; c < NCH_W; c++) {
        const int p = c & 1, pn = p ^ 1;
        cp_wait<0>();
        __syncthreads();
        if (c + 1 < NCH_W) {
            const int kb = (c + 1) * KC;
#pragma unroll
            for (int i = 0; i < 4; i++) cp16(smb + WH_A(pn, a_p[i]) + a_doff[i], a_src[i] + kb);
#pragma unroll
            for (int i = 0; i < 2; i++) cp16(smb + WH_B(pn, b_p[i]) + b_doff[i], b_src[i] + kb);
            cp_commit();
        }
        uint32_t afh[2][4], afl[2][4];
        ldm4(afh[0], smb + WH_A(p, 0) + aRow);
        ldm4(afh[1], smb + WH_A(p, 0) + aRow + 32);
        ldm4(afl[0], smb + WH_A(p, 1) + aRow);
        ldm4(afl[1], smb + WH_A(p, 1) + aRow + 32);
#pragma unroll
        for (int j = 0; j < 8; j++) {
            uint32_t bh[4], bl[4];
            ldm4(bh, smb + WH_B(p, 0) + j * 8 * (BSTR * 2) + bRow);
            ldm4(bl, smb + WH_B(p, 1) + j * 8 * (BSTR * 2) + bRow);
            mma_bf16(acc[j], afh[0], bh[0], bh[1]);
            mma_bf16(acc[j], afh[0], bl[0], bl[1]);
            mma_bf16(acc[j], afl[0], bh[0], bh[1]);
            mma_bf16(acc[j], afh[1], bh[2], bh[3]);
            mma_bf16(acc[j], afh[1], bl[2], bl[3]);
            mma_bf16(acc[j], afl[1], bh[2], bh[3]);
        }
    }

    const int g = lane >> 2;
    const int row0 = nbase + 16 * wid + g;
    float* o0 = g_Wh + ((size_t)h * N_NODES + row0) * OUT_F + (lane & 3) * 2;
    float* o1 = o0 + 8 * OUT_F;
#pragma unroll
    for (int j = 0; j < 8; j++) {
        *(float2*)(o0 + j * 8) = make_float2(acc[j][0], acc[j][1]);
        *(float2*)(o1 + j * 8) = make_float2(acc[j][2], acc[j][3]);
    }
}

// ---------------- kernel: f1/f2 + unshifted exp tables ----------------
__global__ void attn_vec_kernel(const float* __restrict__ a1,
                                const float* __restrict__ a2) {
    int gw = (blockIdx.x * blockDim.x + threadIdx.x) >> 5;
    int lane = threadIdx.x & 31;
    if (gw >= HEADS * N_NODES) return;
    int h = gw >> 12;
    int n = gw & (N_NODES - 1);
    const float* whp = &g_Wh[(h * N_NODES + n) * OUT_F];
    float w0 = whp[lane], w1 = whp[lane + 32];
    float s1 = w0 * a1[h * OUT_F + lane] + w1 * a1[h * OUT_F + lane + 32];
    float s2 = w0 * a2[h * OUT_F + lane] + w1 * a2[h * OUT_F + lane + 32];
#pragma unroll
    for (int off = 16; off; off >>= 1) {
        s1 += __shfl_xor_sync(0xffffffffu, s1, off);
        s2 += __shfl_xor_sync(0xffffffffu, s2, off);
    }
    if (lane == 0) {
        int idx = h * N_NODES + n;
        g_f1[idx] = s1;
        g_f2[idx] = s2;
        g_P2[idx] = expf(s2);
        g_Q2[idx] = expf(ALPHA * s2);
    }
}

// ---------------- kernel: per-head max of f2 ----------------
__global__ __launch_bounds__(256) void maxf2_kernel() {
    __shared__ float red[256];
    const int h = blockIdx.x, t = threadIdx.x;
    float m = -3.4e38f;
#pragma unroll
    for (int i = 0; i < 16; i++) m = fmaxf(m, g_f2[h * N_NODES + t + i * 256]);
    red[t] = m;
    __syncthreads();
    for (int s = 128; s; s >>= 1) {
        if (t < s) red[t] = fmaxf(red[t], red[t + s]);
        __syncthreads();
    }
    if (t == 0) g_mx[h] = red[0];
}

// ---------------- kernel: shifted P1/Q1 ----------------
__global__ __launch_bounds__(256) void exp1_kernel() {
    int idx = blockIdx.x * blockDim.x + threadIdx.x;
    int h = idx >> 12;
    float f1 = g_f1[idx];
    float s = f1 + g_mx[h];
    float M = s > 0.f ? s : ALPHA * s;
    g_P1[idx] = expf(f1 - M);
    g_Q1[idx] = expf(ALPHA * f1 - M);
}

// ---------------- kernel: transpose + fp16 convert of Wh ----------------
__global__ __launch_bounds__(256) void whT_split_kernel() {
    __shared__ float T[64 * 65];
    const int h = blockIdx.y;
    const int mb = blockIdx.x * 64;
    const int t = threadIdx.x;
    const float* src = g_Wh + ((size_t)h * N_NODES + mb) * OUT_F;
#pragma unroll
    for (int i = 0; i < 16; i++) {
        int lin = t + i * 256;
        int m = lin >> 6, o = lin & 63;
        T[m * 65 + o] = src[lin];
    }
    __syncthreads();
#pragma unroll
    for (int i = 0; i < 8; i++) {
        int lin = t + i * 256;
        int o = lin >> 5, mp = lin & 31;
        __half2 h2 = __floats2half2_rn(T[(2 * mp) * 65 + o], T[(2 * mp + 1) * 65 + o]);
        size_t dst = ((size_t)h * OUT_F + o) * N_NODES + mb + 2 * mp;
        *reinterpret_cast<unsigned*>(&g_WhT_h16[dst]) = *reinterpret_cast<unsigned*>(&h2);
    }
}

// ---------------- kernel: fp16 HMMA fused masked-softmax aggregation ----------------
// 128 rows x 64 cols per CTA; KC2=64; 8 warps, warp tile 32 rows x 32 cols.
__global__ __launch_bounds__(256, 2) void gat_mma_kernel(float* __restrict__ out) {
    extern __shared__ __align__(16) char sm[];
    const int t = threadIdx.x;
    const int wid = t >> 5, lane = t & 31;
    const int h = blockIdx.y;
    const int nbase = blockIdx.x * GAT_RT;
    const int hN = h * N_NODES;
    const uint32_t smb = smem_u32(sm);

    // ---- w-gen assignment: 4 rows x 8 m per thread ----
    const int rg = t >> 3;           // row group 0..31 -> rows rg*4..+3
    const int mo = t & 7;            // m-oct 0..7 -> m mo*8..+7
    float F1r[4], P1r[4], Q1r[4];
    const unsigned* adjr[4];
#pragma unroll
    for (int i = 0; i < 4; i++) {
        int grow = nbase + rg * 4 + i;
        F1r[i] = g_f1[hN + grow];
        P1r[i] = g_P1[hN + grow];
        Q1r[i] = g_Q1[hN + grow];
        adjr[i] = g_adjbits + (size_t)grow * (N_NODES / 32);
    }
    float Dacc[4] = {0.f, 0.f, 0.f, 0.f};

    const __half* whTh = g_WhT_h16 + ((size_t)h * OUT_F) * N_NODES;

    // B staging: 512 quads ([64 o][8 quads]), 2 per thread
    const __half* b_src[2];
    uint32_t b_doff[2];
#pragma unroll
    for (int i = 0; i < 2; i++) {
        int idx = t * 2 + i;
        int br = idx >> 3, bq = idx & 7;
        b_src[i] = whTh + (size_t)br * N_NODES + bq * 8;
        b_doff[i] = (uint32_t)(br * (AST2 * 2) + bq * 16);
    }

    // w-gen chunk cn -> A buffer buf (4 rows x 8 m fp16 per thread)
    auto wgen = [&](int cn, int buf) {
        const int mb = cn * KC2 + mo * 8;
        const int word = cn * 2 + (mo >> 2);
        const int bitbase = (mo & 3) * 8;
        float4 f2a = *(const float4*)(g_f2 + hN + mb);
        float4 f2b = *(const float4*)(g_f2 + hN + mb + 4);
        float4 p2a = *(const float4*)(g_P2 + hN + mb);
        float4 p2b = *(const float4*)(g_P2 + hN + mb + 4);
        float4 q2a = *(const float4*)(g_Q2 + hN + mb);
        float4 q2b = *(const float4*)(g_Q2 + hN + mb + 4);
        float fv[8] = {f2a.x, f2a.y, f2a.z, f2a.w, f2b.x, f2b.y, f2b.z, f2b.w};
        float pv[8] = {p2a.x, p2a.y, p2a.z, p2a.w, p2b.x, p2b.y, p2b.z, p2b.w};
        float qv[8] = {q2a.x, q2a.y, q2a.z, q2a.w, q2b.x, q2b.y, q2b.z, q2b.w};
#pragma unroll
        for (int i = 0; i < 4; i++) {
            const unsigned aw = adjr[i][word] >> bitbase;
            float wv[8];
            float ds = 0.f;
#pragma unroll
            for (int e = 0; e < 8; e++) {
                float pos = F1r[i] + fv[e];
                float w = (pos > 0.f) ? (P1r[i] * pv[e]) : (Q1r[i] * qv[e]);
                w = ((aw >> e) & 1u) ? w : 0.f;
                ds += w;
                wv[e] = w;
            }
            Dacc[i] += ds;
            unsigned hp[4];
#pragma unroll
            for (int e = 0; e < 4; e++) {
                __half2 h2 = __floats2half2_rn(wv[2 * e], wv[2 * e + 1]);
                hp[e] = *reinterpret_cast<unsigned*>(&h2);
            }
            const uint32_t dst =
                smb + GA_A(buf) + (rg * 4 + i) * (AST2 * 2) + mo * 16;
            asm volatile("st.shared.v4.b32 [%0], {%1, %2, %3, %4};"
                         :: "r"(dst), "r"(hp[0]), "r"(hp[1]), "r"(hp[2]), "r"(hp[3])
                         : "memory");
        }
    };

    // prologue
#pragma unroll
    for (int i = 0; i < 2; i++) cp16(smb + GA_B(0) + b_doff[i], b_src[i]);
    cp_commit();
    wgen(0, 0);
    cp_wait<0>();
    __syncthreads();

    float acc[2][4][4];
#pragma unroll
    for (int f = 0; f < 2; f++)
#pragma unroll
        for (int j = 0; j < 4; j++)
#pragma unroll
            for (int e = 0; e < 4; e++) acc[f][j][e] = 0.f;

    const int rgrp = wid & 3;        // 32-row group
    const int chalf = wid >> 2;      // 32-col half
    const uint32_t aRow0 = (rgrp * 32 + (lane & 15)) * (AST2 * 2) + (lane >> 4) * 16;
    const uint32_t aRow1 = aRow0 + 16 * (AST2 * 2);
    const uint32_t bOff = (chalf * 32 + (lane & 7)) * (AST2 * 2) + (lane >> 3) * 16;

    for (int c = 0; c < NCH2; c++) {
        const int p = c & 1, pn = p ^ 1;
        if (c + 1 < NCH2) {
            const int mb2 = (c + 1) * KC2;
#pragma unroll
            for (int i = 0; i < 2; i++) cp16(smb + GA_B(pn) + b_doff[i], b_src[i] + mb2);
            cp_commit();
        }
        uint32_t af[2][4][4];
#pragma unroll
        for (int s = 0; s < 4; s++) {
            ldm4(af[0][s], smb + GA_A(p) + aRow0 + s * 32);
            ldm4(af[1][s], smb + GA_A(p) + aRow1 + s * 32);
        }
#pragma unroll
        for (int j = 0; j < 4; j++) {
            uint32_t b0[4], b1[4];
            const uint32_t bj = smb + GA_B(p) + j * 8 * (AST2 * 2) + bOff;
            ldm4(b0, bj);
            ldm4(b1, bj + 64);
            mma_f16(acc[0][j], af[0][0], b0[0], b0[1]);
            mma_f16(acc[1][j], af[1][0], b0[0], b0[1]);
            mma_f16(acc[0][j], af[0][1], b0[2], b0[3]);
            mma_f16(acc[1][j], af[1][1], b0[2], b0[3]);
            mma_f16(acc[0][j], af[0][2], b1[0], b1[1]);
            mma_f16(acc[1][j], af[1][2], b1[0], b1[1]);
            mma_f16(acc[0][j], af[0][3], b1[2], b1[3]);
            mma_f16(acc[1][j], af[1][3], b1[2], b1[3]);
        }
        if (c + 1 < NCH2) wgen(c + 1, pn);
        cp_wait<0>();
        __syncthreads();
    }

    // ---- denominator: Dsh[row][mo] partials, then per-row sum ----
    float* Dsh = (float*)(sm + GA_DSH);
#pragma unroll
    for (int i = 0; i < 4; i++) Dsh[(rg * 4 + i) * 8 + mo] = Dacc[i];
    __syncthreads();

    const int g = lane >> 2;
#pragma unroll
    for (int f = 0; f < 2; f++) {
        const int r0 = rgrp * 32 + f * 16 + g;
        const int r1 = r0 + 8;
        float s0 = 0.f, s1 = 0.f;
#pragma unroll
        for (int k = 0; k < 8; k++) {
            s0 += Dsh[r0 * 8 + k];
            s1 += Dsh[r1 * 8 + k];
        }
        const float inv0 = 1.0f / s0;
        const float inv1 = 1.0f / s1;
        float* o0 = out + (size_t)(nbase + r0) * (HEADS * OUT_F) + h * OUT_F + chalf * 32 +
                    (lane & 3) * 2;
        float* o1 = out + (size_t)(nbase + r1) * (HEADS * OUT_F) + h * OUT_F + chalf * 32 +
                    (lane & 3) * 2;
#pragma unroll
        for (int j = 0; j < 4; j++) {
            *(float2*)(o0 + j * 8) = make_float2(acc[f][j][0] * inv0, acc[f][j][1] * inv0);
            *(float2*)(o1 + j * 8) = make_float2(acc[f][j][2] * inv1, acc[f][j][3] * inv1);
        }
    }
}

// ---------------- launch ----------------
extern "C" void kernel_launch(void* const* d_in, const int* in_sizes, int n_in,
                              void* d_out, int out_size) {
    const float* x   = (const float*)d_in[0];
    const int*   adj = (const int*)d_in[1];
    const float* W   = (const float*)d_in[2];
    const float* a1  = (const float*)d_in[3];
    const float* a2  = (const float*)d_in[4];
    float* out = (float*)d_out;

    cudaFuncSetAttribute(wh_mma_kernel, cudaFuncAttributeMaxDynamicSharedMemorySize,
                         WH_SMEM);
    cudaFuncSetAttribute(gat_mma_kernel, cudaFuncAttributeMaxDynamicSharedMemorySize,
                         GA_SMEM);

    bitpack_kernel<<<(N_NODES * N_NODES / 32) / 256, 256>>>(adj);
    xsplit_kernel<<<(N_NODES * IN_F) / (256 * 8), 256>>>(x);
    wsplit_kernel<<<HEADS, 256>>>(W);

    dim3 gW(N_NODES / RT, HEADS);
    wh_mma_kernel<<<gW, 256, WH_SMEM>>>();

    attn_vec_kernel<<<(HEADS * N_NODES * 32) / 256, 256>>>(a1, a2);
    maxf2_kernel<<<HEADS, 256>>>();
    exp1_kernel<<<(HEADS * N_NODES) / 256, 256>>>();

    dim3 gT(N_NODES / 64, HEADS);
    whT_split_kernel<<<gT, 256>>>();

    dim3 gD(N_NODES / GAT_RT, HEADS);
    gat_mma_kernel<<<gD, 256, GA_SMEM>>>(out);
}

// round 9
// speedup vs baseline: 1.0515x; 1.0515x over previous
#include <cuda_runtime.h>
#include <cuda_bf16.h>
#include <cuda_fp16.h>
#include <cstdint>

#define N_NODES 4096
#define IN_F 512
#define OUT_F 64
#define HEADS 8
#define ALPHA 0.2f

#define RT 128                 // rows per CTA (wh kernel)
#define KC 32                  // k per chunk (wh kernel)
#define NCH_W (IN_F / KC)      // 16 chunks (wh)
#define ASTR 40                // padded bf16 row stride (80 B) (wh kernel)
#define BSTR 40

// ---- wh dynamic smem offsets ----
#define WH_A(buf, prec) ((buf) * 20480 + (prec) * 10240)
#define WH_B(buf, prec) (40960 + (buf) * 10240 + (prec) * 5120)
#define WH_SMEM 61440

// ---- gat (fp16, 64x64 tile, KC2=64, smem-staged tables) ----
#define GAT_RT 64
#define KC2 64
#define NCH2 (N_NODES / KC2)   // 64 chunks
#define AST2 72                // fp16 stride (144 B)
#define GA_A(buf) ((buf) * 9216)            // [64][72] fp16
#define GA_B(buf) (18432 + (buf) * 9216)    // [64][72] fp16
#define GA_T(tb)  (36864 + (tb) * 768)      // [3][64] float tables, 3 bufs
#define GA_DSH 39168                        // 256 floats
#define GA_SMEM 40192

// ---------------- scratch (device globals; no allocation) ----------------
__device__ __align__(16) float g_Wh[HEADS * N_NODES * OUT_F];          // 8 MB [h][n][o]
__device__ float g_f1[HEADS * N_NODES];
__device__ float g_f2[HEADS * N_NODES];
__device__ float g_P1[HEADS * N_NODES];   // exp(f1 - M)  (shifted)
__device__ float g_P2[HEADS * N_NODES];   // exp(f2)
__device__ float g_Q1[HEADS * N_NODES];   // exp(a*f1 - M)
__device__ float g_Q2[HEADS * N_NODES];   // exp(a*f2)
__device__ float g_mx[HEADS];             // per-head max f2
__device__ unsigned g_adjbits[N_NODES * (N_NODES / 32)];               // 2 MB
__device__ __align__(16) __half g_WhT_h16[HEADS * OUT_F * N_NODES];    // 4 MB [h][o][m]
__device__ __align__(16) __nv_bfloat16 g_x_hi[N_NODES * IN_F];         // 4 MB [n][k]
__device__ __align__(16) __nv_bfloat16 g_x_lo[N_NODES * IN_F];
__device__ __align__(16) __nv_bfloat16 g_WT_hi[HEADS * OUT_F * IN_F];  // 512 KB [h][o][k]
__device__ __align__(16) __nv_bfloat16 g_WT_lo[HEADS * OUT_F * IN_F];

// ---------------- helpers ----------------
__device__ __forceinline__ uint32_t smem_u32(const void* p) {
    uint32_t a;
    asm("{ .reg .u64 t; cvta.to.shared.u64 t, %1; cvt.u32.u64 %0, t; }" : "=r"(a) : "l"(p));
    return a;
}
__device__ __forceinline__ void cp16(uint32_t dst, const void* src) {
    asm volatile("cp.async.cg.shared.global [%0], [%1], 16;" :: "r"(dst), "l"(src) : "memory");
}
__device__ __forceinline__ void cp_commit() {
    asm volatile("cp.async.commit_group;" ::: "memory");
}
template <int N>
__device__ __forceinline__ void cp_wait() {
    asm volatile("cp.async.wait_group %0;" :: "n"(N) : "memory");
}
__device__ __forceinline__ void ldm4(uint32_t* r, uint32_t addr) {
    asm volatile("ldmatrix.sync.aligned.m8n8.x4.shared.b16 {%0,%1,%2,%3}, [%4];"
                 : "=r"(r[0]), "=r"(r[1]), "=r"(r[2]), "=r"(r[3]) : "r"(addr) : "memory");
}
__device__ __forceinline__ void mma_bf16(float* c, const uint32_t* a, uint32_t b0,
                                         uint32_t b1) {
    asm("mma.sync.aligned.m16n8k16.row.col.f32.bf16.bf16.f32 "
        "{%0,%1,%2,%3}, {%4,%5,%6,%7}, {%8,%9}, {%0,%1,%2,%3};"
        : "+f"(c[0]), "+f"(c[1]), "+f"(c[2]), "+f"(c[3])
        : "r"(a[0]), "r"(a[1]), "r"(a[2]), "r"(a[3]), "r"(b0), "r"(b1));
}
__device__ __forceinline__ void mma_f16(float* c, const uint32_t* a, uint32_t b0,
                                        uint32_t b1) {
    asm("mma.sync.aligned.m16n8k16.row.col.f32.f16.f16.f32 "
        "{%0,%1,%2,%3}, {%4,%5,%6,%7}, {%8,%9}, {%0,%1,%2,%3};"
        : "+f"(c[0]), "+f"(c[1]), "+f"(c[2]), "+f"(c[3])
        : "r"(a[0]), "r"(a[1]), "r"(a[2]), "r"(a[3]), "r"(b0), "r"(b1));
}
__device__ __forceinline__ void split_pair(float x, float y, unsigned& hi, unsigned& lo) {
    __nv_bfloat162 h2 = __float22bfloat162_rn(make_float2(x, y));
    float2 hf = __bfloat1622float2(h2);
    __nv_bfloat162 l2 = __float22bfloat162_rn(make_float2(x - hf.x, y - hf.y));
    hi = *reinterpret_cast<unsigned*>(&h2);
    lo = *reinterpret_cast<unsigned*>(&l2);
}

// ---------------- kernel: bit-pack adjacency ----------------
__global__ __launch_bounds__(256) void bitpack_kernel(const int* __restrict__ adj) {
    int t = blockIdx.x * blockDim.x + threadIdx.x;
    const int4* p = (const int4*)adj + (size_t)t * 8;
    unsigned w = 0;
#pragma unroll
    for (int i = 0; i < 8; i++) {
        int4 v = p[i];
        w |= (v.x > 0 ? 1u : 0u) << (4 * i);
        w |= (v.y > 0 ? 1u : 0u) << (4 * i + 1);
        w |= (v.z > 0 ? 1u : 0u) << (4 * i + 2);
        w |= (v.w > 0 ? 1u : 0u) << (4 * i + 3);
    }
    g_adjbits[t] = w;
}

// ---------------- kernel: split x into bf16 hi/lo ----------------
__global__ __launch_bounds__(256) void xsplit_kernel(const float* __restrict__ x) {
    int gid = blockIdx.x * blockDim.x + threadIdx.x;
    const float4* xp = (const float4*)x + gid * 2;
    float4 v0 = xp[0], v1 = xp[1];
    float f[8] = {v0.x, v0.y, v0.z, v0.w, v1.x, v1.y, v1.z, v1.w};
    unsigned hw[4], lw[4];
#pragma unroll
    for (int i = 0; i < 4; i++) split_pair(f[2 * i], f[2 * i + 1], hw[i], lw[i]);
    *(uint4*)(g_x_hi + (size_t)gid * 8) = make_uint4(hw[0], hw[1], hw[2], hw[3]);
    *(uint4*)(g_x_lo + (size_t)gid * 8) = make_uint4(lw[0], lw[1], lw[2], lw[3]);
}

// ---------------- kernel: transpose + split W -> WT[h][o][k] ----------------
__global__ __launch_bounds__(256) void wsplit_kernel(const float* __restrict__ W) {
    const int h = blockIdx.x;
    const int t = threadIdx.x;
#pragma unroll 4
    for (int i = 0; i < 128; i++) {
        int lin = i * 256 + t;
        int o = lin >> 9, k = lin & 511;
        float v = W[((size_t)h * IN_F + k) * OUT_F + o];
        __nv_bfloat16 hb = __float2bfloat16(v);
        __nv_bfloat16 lb = __float2bfloat16(v - __bfloat162float(hb));
        size_t d = ((size_t)h * OUT_F + o) * IN_F + k;
        g_WT_hi[d] = hb;
        g_WT_lo[d] = lb;
    }
}

// ---------------- kernel: Wh = x @ W via HMMA (3-term bf16 split) ----------------
__global__ __launch_bounds__(256, 2) void wh_mma_kernel() {
    extern __shared__ __align__(16) char sm[];
    const int t = threadIdx.x;
    const int wid = t >> 5, lane = t & 31;
    const int h = blockIdx.y;
    const int nbase = blockIdx.x * RT;

    const int a_p[4] = {(t * 4) >> 9, (t * 4 + 1) >> 9, (t * 4 + 2) >> 9, (t * 4 + 3) >> 9};
    int a_r[4], a_q[4];
    const __nv_bfloat16* a_src[4];
    uint32_t a_doff[4];
#pragma unroll
    for (int i = 0; i < 4; i++) {
        int idx = t * 4 + i;
        a_r[i] = (idx >> 2) & 127;
        a_q[i] = idx & 3;
        a_src[i] = (a_p[i] ? g_x_lo : g_x_hi) + (size_t)(nbase + a_r[i]) * IN_F + a_q[i] * 8;
        a_doff[i] = (uint32_t)(a_r[i] * (ASTR * 2) + a_q[i] * 16);
    }
    int b_p[2];
    const __nv_bfloat16* b_src[2];
    uint32_t b_doff[2];
#pragma unroll
    for (int i = 0; i < 2; i++) {
        int idx = t * 2 + i;
        b_p[i] = idx >> 8;
        int br = (idx >> 2) & 63, bq = idx & 3;
        b_src[i] = (b_p[i] ? g_WT_lo : g_WT_hi) + ((size_t)h * OUT_F + br) * IN_F + bq * 8;
        b_doff[i] = (uint32_t)(br * (BSTR * 2) + bq * 16);
    }
    const uint32_t smb = smem_u32(sm);

#pragma unroll
    for (int i = 0; i < 4; i++) cp16(smb + WH_A(0, a_p[i]) + a_doff[i], a_src[i]);
#pragma unroll
    for (int i = 0; i < 2; i++) cp16(smb + WH_B(0, b_p[i]) + b_doff[i], b_src[i]);
    cp_commit();

    float acc[8][4];
#pragma unroll
    for (int j = 0; j < 8; j++)
#pragma unroll
        for (int q = 0; q < 4; q++) acc[j][q] = 0.f;

    const uint32_t aRow = (16 * wid + (lane & 15)) * (ASTR * 2) + (lane >> 4) * 16;
    const uint32_t bRow = (lane & 7) * (BSTR * 2) + (lane >> 3) * 16;

    for (int c = 0; c < NCH_W; c++) {
        const int p = c & 1, pn = p ^ 1;
        cp_wait<0>();
        __syncthreads();
        if (c + 1 < NCH_W) {
            const int kb = (c + 1) * KC;
#pragma unroll
            for (int i = 0; i < 4; i++) cp16(smb + WH_A(pn, a_p[i]) + a_doff[i], a_src[i] + kb);
#pragma unroll
            for (int i = 0; i < 2; i++) cp16(smb + WH_B(pn, b_p[i]) + b_doff[i], b_src[i] + kb);
            cp_commit();
        }
        uint32_t afh[2][4], afl[2][4];
        ldm4(afh[0], smb + WH_A(p, 0) + aRow);
        ldm4(afh[1], smb + WH_A(p, 0) + aRow + 32);
        ldm4(afl[0], smb + WH_A(p, 1) + aRow);
        ldm4(afl[1], smb + WH_A(p, 1) + aRow + 32);
#pragma unroll
        for (int j = 0; j < 8; j++) {
            uint32_t bh[4], bl[4];
            ldm4(bh, smb + WH_B(p, 0) + j * 8 * (BSTR * 2) + bRow);
            ldm4(bl, smb + WH_B(p, 1) + j * 8 * (BSTR * 2) + bRow);
            mma_bf16(acc[j], afh[0], bh[0], bh[1]);
            mma_bf16(acc[j], afh[0], bl[0], bl[1]);
            mma_bf16(acc[j], afl[0], bh[0], bh[1]);
            mma_bf16(acc[j], afh[1], bh[2], bh[3]);
            mma_bf16(acc[j], afh[1], bl[2], bl[3]);
            mma_bf16(acc[j], afl[1], bh[2], bh[3]);
        }
    }

    const int g = lane >> 2;
    const int row0 = nbase + 16 * wid + g;
    float* o0 = g_Wh + ((size_t)h * N_NODES + row0) * OUT_F + (lane & 3) * 2;
    float* o1 = o0 + 8 * OUT_F;
#pragma unroll
    for (int j = 0; j < 8; j++) {
        *(float2*)(o0 + j * 8) = make_float2(acc[j][0], acc[j][1]);
        *(float2*)(o1 + j * 8) = make_float2(acc[j][2], acc[j][3]);
    }
}

// ---------------- kernel: f1/f2 + unshifted exp tables ----------------
__global__ void attn_vec_kernel(const float* __restrict__ a1,
                                const float* __restrict__ a2) {
    int gw = (blockIdx.x * blockDim.x + threadIdx.x) >> 5;
    int lane = threadIdx.x & 31;
    if (gw >= HEADS * N_NODES) return;
    int h = gw >> 12;
    int n = gw & (N_NODES - 1);
    const float* whp = &g_Wh[(h * N_NODES + n) * OUT_F];
    float w0 = whp[lane], w1 = whp[lane + 32];
    float s1 = w0 * a1[h * OUT_F + lane] + w1 * a1[h * OUT_F + lane + 32];
    float s2 = w0 * a2[h * OUT_F + lane] + w1 * a2[h * OUT_F + lane + 32];
#pragma unroll
    for (int off = 16; off; off >>= 1) {
        s1 += __shfl_xor_sync(0xffffffffu, s1, off);
        s2 += __shfl_xor_sync(0xffffffffu, s2, off);
    }
    if (lane == 0) {
        int idx = h * N_NODES + n;
        g_f1[idx] = s1;
        g_f2[idx] = s2;
        g_P2[idx] = expf(s2);
        g_Q2[idx] = expf(ALPHA * s2);
    }
}

// ---------------- kernel: per-head max of f2 ----------------
__global__ __launch_bounds__(256) void maxf2_kernel() {
    __shared__ float red[256];
    const int h = blockIdx.x, t = threadIdx.x;
    float m = -3.4e38f;
#pragma unroll
    for (int i = 0; i < 16; i++) m = fmaxf(m, g_f2[h * N_NODES + t + i * 256]);
    red[t] = m;
    __syncthreads();
    for (int s = 128; s; s >>= 1) {
        if (t < s) red[t] = fmaxf(red[t], red[t + s]);
        __syncthreads();
    }
    if (t == 0) g_mx[h] = red[0];
}

// ---------------- kernel: shifted P1/Q1 ----------------
__global__ __launch_bounds__(256) void exp1_kernel() {
    int idx = blockIdx.x * blockDim.x + threadIdx.x;
    int h = idx >> 12;
    float f1 = g_f1[idx];
    float s = f1 + g_mx[h];
    float M = s > 0.f ? s : ALPHA * s;
    g_P1[idx] = expf(f1 - M);
    g_Q1[idx] = expf(ALPHA * f1 - M);
}

// ---------------- kernel: transpose + fp16 convert of Wh ----------------
__global__ __launch_bounds__(256) void whT_split_kernel() {
    __shared__ float T[64 * 65];
    const int h = blockIdx.y;
    const int mb = blockIdx.x * 64;
    const int t = threadIdx.x;
    const float* src = g_Wh + ((size_t)h * N_NODES + mb) * OUT_F;
#pragma unroll
    for (int i = 0; i < 16; i++) {
        int lin = t + i * 256;
        int m = lin >> 6, o = lin & 63;
        T[m * 65 + o] = src[lin];
    }
    __syncthreads();
#pragma unroll
    for (int i = 0; i < 8; i++) {
        int lin = t + i * 256;
        int o = lin >> 5, mp = lin & 31;
        __half2 h2 = __floats2half2_rn(T[(2 * mp) * 65 + o], T[(2 * mp + 1) * 65 + o]);
        size_t dst = ((size_t)h * OUT_F + o) * N_NODES + mb + 2 * mp;
        *reinterpret_cast<unsigned*>(&g_WhT_h16[dst]) = *reinterpret_cast<unsigned*>(&h2);
    }
}

// ---------------- kernel: fp16 HMMA fused masked-softmax aggregation ----------------
// 64 rows x 64 cols per CTA; KC2=64; tables staged in SMEM (triple-buffered).
__global__ __launch_bounds__(256, 3) void gat_mma_kernel(float* __restrict__ out) {
    extern __shared__ __align__(16) char sm[];
    const int t = threadIdx.x;
    const int wid = t >> 5, lane = t & 31;
    const int h = blockIdx.y;
    const int nbase = blockIdx.x * GAT_RT;
    const int hN = h * N_NODES;
    const uint32_t smb = smem_u32(sm);

    // w-gen assignment: row rr (0..63), quarter q -> 16 m's
    const int rr = t >> 2;
    const int q = t & 3;
    const int grow = nbase + rr;
    const float F1r = g_f1[hN + grow];
    const float P1r = g_P1[hN + grow];
    const float Q1r = g_Q1[hN + grow];
    const unsigned* adjrow = g_adjbits + (size_t)grow * (N_NODES / 32);
    float Dacc = 0.f;

    const __half* whTh = g_WhT_h16 + ((size_t)h * OUT_F) * N_NODES;

    // B staging: 512 quads ([64 o][8 quads]), 2 per thread
    const __half* b_src[2];
    uint32_t b_doff[2];
#pragma unroll
    for (int i = 0; i < 2; i++) {
        int idx = t * 2 + i;
        int br = idx >> 3, bq = idx & 7;
        b_src[i] = whTh + (size_t)br * N_NODES + bq * 8;
        b_doff[i] = (uint32_t)(br * (AST2 * 2) + bq * 16);
    }

    // table staging: chunk cn -> GA_T(cn % 3); 48 quads, threads 0..47
    auto stageT = [&](int cn) {
        if (t < 48) {
            int tb = cn % 3;
            int table = t >> 4, q4 = t & 15;
            const float* base = (table == 0) ? g_f2 : ((table == 1) ? g_P2 : g_Q2);
            cp16(smb + GA_T(tb) + table * 256 + q4 * 16, base + hN + cn * KC2 + q4 * 4);
        }
    };

    // w-gen from SMEM tables -> A buffer `buf` (16 fp16 weights per thread)
    auto wgen = [&](int buf, int tb, unsigned awfull) {
        const float* Tf = (const float*)(sm + GA_T(tb));
        const unsigned aw = awfull >> ((q & 1) * 16);
        const uint32_t dst = smb + GA_A(buf) + rr * (AST2 * 2) + q * 32;
#pragma unroll
        for (int g4 = 0; g4 < 2; g4++) {
            float fv[8], pv[8], qv[8];
            *(float4*)&fv[0] = *(const float4*)&Tf[q * 16 + g4 * 8];
            *(float4*)&fv[4] = *(const float4*)&Tf[q * 16 + g4 * 8 + 4];
            *(float4*)&pv[0] = *(const float4*)&Tf[64 + q * 16 + g4 * 8];
            *(float4*)&pv[4] = *(const float4*)&Tf[64 + q * 16 + g4 * 8 + 4];
            *(float4*)&qv[0] = *(const float4*)&Tf[128 + q * 16 + g4 * 8];
            *(float4*)&qv[4] = *(const float4*)&Tf[128 + q * 16 + g4 * 8 + 4];
            float wv[8];
            float ds = 0.f;
#pragma unroll
            for (int e = 0; e < 8; e++) {
                int bit = g4 * 8 + e;
                float pos = F1r + fv[e];
                float w = (pos > 0.f) ? (P1r * pv[e]) : (Q1r * qv[e]);
                w = ((aw >> bit) & 1u) ? w : 0.f;
                ds += w;
                wv[e] = w;
            }
            Dacc += ds;
            unsigned hp[4];
#pragma unroll
            for (int e = 0; e < 4; e++) {
                __half2 h2 = __floats2half2_rn(wv[2 * e], wv[2 * e + 1]);
                hp[e] = *reinterpret_cast<unsigned*>(&h2);
            }
            asm volatile("st.shared.v4.b32 [%0], {%1, %2, %3, %4};"
                         :: "r"(dst + g4 * 16), "r"(hp[0]), "r"(hp[1]), "r"(hp[2]),
                            "r"(hp[3]) : "memory");
        }
    };

    // ---- prologue: B(0), T(0), T(1); then wgen(0) ----
#pragma unroll
    for (int i = 0; i < 2; i++) cp16(smb + GA_B(0) + b_doff[i], b_src[i]);
    stageT(0);
    stageT(1);
    cp_commit();
    cp_wait<0>();
    __syncthreads();
    {
        unsigned aw0 = adjrow[q >> 1];
        wgen(0, 0, aw0);
    }

    float acc[4][4];
#pragma unroll
    for (int j = 0; j < 4; j++)
#pragma unroll
        for (int e = 0; e < 4; e++) acc[j][e] = 0.f;

    const uint32_t aRow = (16 * (wid & 3) + (lane & 15)) * (AST2 * 2) + (lane >> 4) * 16;
    const int jbase = (wid >> 2) * 32;   // output-column base
    const uint32_t bOff = (jbase + (lane & 7)) * (AST2 * 2) + (lane >> 3) * 16;

    for (int c = 0; c < NCH2; c++) {
        const int p = c & 1, pn = p ^ 1;
        // wait: completes group from previous iteration = {B(c), T(c+1)}
        cp_wait<0>();
        __syncthreads();

        unsigned aw_next = 0;
        if (c + 1 < NCH2) {
            aw_next = adjrow[(c + 1) * 2 + (q >> 1)];
            const int mb2 = (c + 1) * KC2;
#pragma unroll
            for (int i = 0; i < 2; i++) cp16(smb + GA_B(pn) + b_doff[i], b_src[i] + mb2);
            if (c + 2 < NCH2) stageT(c + 2);
            cp_commit();
        }

        // MMA on buffer p
        uint32_t af[4][4];
#pragma unroll
        for (int s = 0; s < 4; s++) ldm4(af[s], smb + GA_A(p) + aRow + s * 32);
#pragma unroll
        for (int j = 0; j < 4; j++) {
            uint32_t b0[4], b1[4];
            const uint32_t bj = smb + GA_B(p) + j * 8 * (AST2 * 2) + bOff;
            ldm4(b0, bj);
            ldm4(b1, bj + 64);
            mma_f16(acc[j], af[0], b0[0], b0[1]);
            mma_f16(acc[j], af[1], b0[2], b0[3]);
            mma_f16(acc[j], af[2], b1[0], b1[1]);
            mma_f16(acc[j], af[3], b1[2], b1[3]);
        }

        // w-gen for next chunk into other A buffer (tables already in SMEM)
        if (c + 1 < NCH2) wgen(pn, (c + 1) % 3, aw_next);
    }

    float* Dsh = (float*)(sm + GA_DSH);
    Dsh[t] = Dacc;
    __syncthreads();

    const int g = lane >> 2;
    const int row0 = 16 * (wid & 3) + g;
    const int row1 = row0 + 8;
    const float inv0 =
        1.0f / (Dsh[4 * row0] + Dsh[4 * row0 + 1] + Dsh[4 * row0 + 2] + Dsh[4 * row0 + 3]);
    const float inv1 =
        1.0f / (Dsh[4 * row1] + Dsh[4 * row1 + 1] + Dsh[4 * row1 + 2] + Dsh[4 * row1 + 3]);
    float* o0 = out + (size_t)(nbase + row0) * (HEADS * OUT_F) + h * OUT_F + jbase +
                (lane & 3) * 2;
    float* o1 = out + (size_t)(nbase + row1) * (HEADS * OUT_F) + h * OUT_F + jbase +
                (lane & 3) * 2;
#pragma unroll
    for (int j = 0; j < 4; j++) {
        *(float2*)(o0 + j * 8) = make_float2(acc[j][0] * inv0, acc[j][1] * inv0);
        *(float2*)(o1 + j * 8) = make_float2(acc[j][2] * inv1, acc[j][3] * inv1);
    }
}

// ---------------- launch ----------------
extern "C" void kernel_launch(void* const* d_in, const int* in_sizes, int n_in,
                              void* d_out, int out_size) {
    const float* x   = (const float*)d_in[0];
    const int*   adj = (const int*)d_in[1];
    const float* W   = (const float*)d_in[2];
    const float* a1  = (const float*)d_in[3];
    const float* a2  = (const float*)d_in[4];
    float* out = (float*)d_out;

    cudaFuncSetAttribute(wh_mma_kernel, cudaFuncAttributeMaxDynamicSharedMemorySize,
                         WH_SMEM);
    cudaFuncSetAttribute(gat_mma_kernel, cudaFuncAttributeMaxDynamicSharedMemorySize,
                         GA_SMEM);

    bitpack_kernel<<<(N_NODES * N_NODES / 32) / 256, 256>>>(adj);
    xsplit_kernel<<<(N_NODES * IN_F) / (256 * 8), 256>>>(x);
    wsplit_kernel<<<HEADS, 256>>>(W);

    dim3 gW(N_NODES / RT, HEADS);
    wh_mma_kernel<<<gW, 256, WH_SMEM>>>();

    attn_vec_kernel<<<(HEADS * N_NODES * 32) / 256, 256>>>(a1, a2);
    maxf2_kernel<<<HEADS, 256>>>();
    exp1_kernel<<<(HEADS * N_NODES) / 256, 256>>>();

    dim3 gT(N_NODES / 64, HEADS);
    whT_split_kernel<<<gT, 256>>>();

    dim3 gD(N_NODES / GAT_RT, HEADS);
    gat_mma_kernel<<<gD, 256, GA_SMEM>>>(out);
}

// round 10
// speedup vs baseline: 1.0743x; 1.0218x over previous
#include <cuda_runtime.h>
#include <cuda_bf16.h>
#include <cuda_fp16.h>
#include <cstdint>

#define N_NODES 4096
#define IN_F 512
#define OUT_F 64
#define HEADS 8
#define ALPHA 0.2f

#define RT 128                 // rows per CTA (wh kernel)
#define KC 32                  // k per chunk (wh kernel)
#define NCH_W (IN_F / KC)      // 16 chunks (wh)
#define ASTR 40                // padded bf16 row stride (80 B) (wh kernel)
#define BSTR 40

// ---- wh dynamic smem offsets ----
#define WH_A(buf, prec) ((buf) * 20480 + (prec) * 10240)
#define WH_B(buf, prec) (40960 + (buf) * 10240 + (prec) * 5120)
#define WH_SMEM 61440

// ---- gat (fp16, 128x64 tile, 512 threads, KC2=64, smem tables) ----
#define GAT_RT 128
#define KC2 64
#define NCH2 (N_NODES / KC2)   // 64 chunks
#define AST2 72                // fp16 stride (144 B)
#define GA_A(buf) ((buf) * 18432)           // [128][72] fp16, 2 bufs
#define GA_B(buf) (36864 + (buf) * 9216)    // [64][72] fp16, 2 bufs
#define GA_T(tb)  (55296 + (tb) * 768)      // [3 tables][64] float, 3 bufs
#define GA_DSH 57600                        // 512 floats
#define GA_SMEM 59904

// ---------------- scratch (device globals; no allocation) ----------------
__device__ __align__(16) float g_Wh[HEADS * N_NODES * OUT_F];          // 8 MB [h][n][o]
__device__ float g_f1[HEADS * N_NODES];
__device__ float g_f2[HEADS * N_NODES];
__device__ float g_P1[HEADS * N_NODES];   // exp(f1 - M)  (shifted)
__device__ float g_P2[HEADS * N_NODES];   // exp(f2)
__device__ float g_Q1[HEADS * N_NODES];   // exp(a*f1 - M)
__device__ float g_Q2[HEADS * N_NODES];   // exp(a*f2)
__device__ float g_mx[HEADS];             // per-head max f2
__device__ unsigned g_adjbits[N_NODES * (N_NODES / 32)];               // 2 MB
__device__ __align__(16) __half g_WhT_h16[HEADS * OUT_F * N_NODES];    // 4 MB [h][o][m]
__device__ __align__(16) __nv_bfloat16 g_x_hi[N_NODES * IN_F];         // 4 MB [n][k]
__device__ __align__(16) __nv_bfloat16 g_x_lo[N_NODES * IN_F];
__device__ __align__(16) __nv_bfloat16 g_WT_hi[HEADS * OUT_F * IN_F];  // 512 KB [h][o][k]
__device__ __align__(16) __nv_bfloat16 g_WT_lo[HEADS * OUT_F * IN_F];

// ---------------- helpers ----------------
__device__ __forceinline__ uint32_t smem_u32(const void* p) {
    uint32_t a;
    asm("{ .reg .u64 t; cvta.to.shared.u64 t, %1; cvt.u32.u64 %0, t; }" : "=r"(a) : "l"(p));
    return a;
}
__device__ __forceinline__ void cp16(uint32_t dst, const void* src) {
    asm volatile("cp.async.cg.shared.global [%0], [%1], 16;" :: "r"(dst), "l"(src) : "memory");
}
__device__ __forceinline__ void cp_commit() {
    asm volatile("cp.async.commit_group;" ::: "memory");
}
template <int N>
__device__ __forceinline__ void cp_wait() {
    asm volatile("cp.async.wait_group %0;" :: "n"(N) : "memory");
}
__device__ __forceinline__ void ldm4(uint32_t* r, uint32_t addr) {
    asm volatile("ldmatrix.sync.aligned.m8n8.x4.shared.b16 {%0,%1,%2,%3}, [%4];"
                 : "=r"(r[0]), "=r"(r[1]), "=r"(r[2]), "=r"(r[3]) : "r"(addr) : "memory");
}
__device__ __forceinline__ void mma_bf16(float* c, const uint32_t* a, uint32_t b0,
                                         uint32_t b1) {
    asm("mma.sync.aligned.m16n8k16.row.col.f32.bf16.bf16.f32 "
        "{%0,%1,%2,%3}, {%4,%5,%6,%7}, {%8,%9}, {%0,%1,%2,%3};"
        : "+f"(c[0]), "+f"(c[1]), "+f"(c[2]), "+f"(c[3])
        : "r"(a[0]), "r"(a[1]), "r"(a[2]), "r"(a[3]), "r"(b0), "r"(b1));
}
__device__ __forceinline__ void mma_f16(float* c, const uint32_t* a, uint32_t b0,
                                        uint32_t b1) {
    asm("mma.sync.aligned.m16n8k16.row.col.f32.f16.f16.f32 "
        "{%0,%1,%2,%3}, {%4,%5,%6,%7}, {%8,%9}, {%0,%1,%2,%3};"
        : "+f"(c[0]), "+f"(c[1]), "+f"(c[2]), "+f"(c[3])
        : "r"(a[0]), "r"(a[1]), "r"(a[2]), "r"(a[3]), "r"(b0), "r"(b1));
}
__device__ __forceinline__ void split_pair(float x, float y, unsigned& hi, unsigned& lo) {
    __nv_bfloat162 h2 = __float22bfloat162_rn(make_float2(x, y));
    float2 hf = __bfloat1622float2(h2);
    __nv_bfloat162 l2 = __float22bfloat162_rn(make_float2(x - hf.x, y - hf.y));
    hi = *reinterpret_cast<unsigned*>(&h2);
    lo = *reinterpret_cast<unsigned*>(&l2);
}

// ---------------- kernel: bit-pack adjacency ----------------
__global__ __launch_bounds__(256) void bitpack_kernel(const int* __restrict__ adj) {
    int t = blockIdx.x * blockDim.x + threadIdx.x;
    const int4* p = (const int4*)adj + (size_t)t * 8;
    unsigned w = 0;
#pragma unroll
    for (int i = 0; i < 8; i++) {
        int4 v = p[i];
        w |= (v.x > 0 ? 1u : 0u) << (4 * i);
        w |= (v.y > 0 ? 1u : 0u) << (4 * i + 1);
        w |= (v.z > 0 ? 1u : 0u) << (4 * i + 2);
        w |= (v.w > 0 ? 1u : 0u) << (4 * i + 3);
    }
    g_adjbits[t] = w;
}

// ---------------- kernel: split x into bf16 hi/lo ----------------
__global__ __launch_bounds__(256) void xsplit_kernel(const float* __restrict__ x) {
    int gid = blockIdx.x * blockDim.x + threadIdx.x;
    const float4* xp = (const float4*)x + gid * 2;
    float4 v0 = xp[0], v1 = xp[1];
    float f[8] = {v0.x, v0.y, v0.z, v0.w, v1.x, v1.y, v1.z, v1.w};
    unsigned hw[4], lw[4];
#pragma unroll
    for (int i = 0; i < 4; i++) split_pair(f[2 * i], f[2 * i + 1], hw[i], lw[i]);
    *(uint4*)(g_x_hi + (size_t)gid * 8) = make_uint4(hw[0], hw[1], hw[2], hw[3]);
    *(uint4*)(g_x_lo + (size_t)gid * 8) = make_uint4(lw[0], lw[1], lw[2], lw[3]);
}

// ---------------- kernel: transpose + split W -> WT[h][o][k] ----------------
__global__ __launch_bounds__(256) void wsplit_kernel(const float* __restrict__ W) {
    const int h = blockIdx.x;
    const int t = threadIdx.x;
#pragma unroll 4
    for (int i = 0; i < 128; i++) {
        int lin = i * 256 + t;
        int o = lin >> 9, k = lin & 511;
        float v = W[((size_t)h * IN_F + k) * OUT_F + o];
        __nv_bfloat16 hb = __float2bfloat16(v);
        __nv_bfloat16 lb = __float2bfloat16(v - __bfloat162float(hb));
        size_t d = ((size_t)h * OUT_F + o) * IN_F + k;
        g_WT_hi[d] = hb;
        g_WT_lo[d] = lb;
    }
}

// ---------------- kernel: Wh = x @ W via HMMA (3-term bf16 split) ----------------
__global__ __launch_bounds__(256, 2) void wh_mma_kernel() {
    extern __shared__ __align__(16) char sm[];
    const int t = threadIdx.x;
    const int wid = t >> 5, lane = t & 31;
    const int h = blockIdx.y;
    const int nbase = blockIdx.x * RT;

    const int a_p[4] = {(t * 4) >> 9, (t * 4 + 1) >> 9, (t * 4 + 2) >> 9, (t * 4 + 3) >> 9};
    int a_r[4], a_q[4];
    const __nv_bfloat16* a_src[4];
    uint32_t a_doff[4];
#pragma unroll
    for (int i = 0; i < 4; i++) {
        int idx = t * 4 + i;
        a_r[i] = (idx >> 2) & 127;
        a_q[i] = idx & 3;
        a_src[i] = (a_p[i] ? g_x_lo : g_x_hi) + (size_t)(nbase + a_r[i]) * IN_F + a_q[i] * 8;
        a_doff[i] = (uint32_t)(a_r[i] * (ASTR * 2) + a_q[i] * 16);
    }
    int b_p[2];
    const __nv_bfloat16* b_src[2];
    uint32_t b_doff[2];
#pragma unroll
    for (int i = 0; i < 2; i++) {
        int idx = t * 2 + i;
        b_p[i] = idx >> 8;
        int br = (idx >> 2) & 63, bq = idx & 3;
        b_src[i] = (b_p[i] ? g_WT_lo : g_WT_hi) + ((size_t)h * OUT_F + br) * IN_F + bq * 8;
        b_doff[i] = (uint32_t)(br * (BSTR * 2) + bq * 16);
    }
    const uint32_t smb = smem_u32(sm);

#pragma unroll
    for (int i = 0; i < 4; i++) cp16(smb + WH_A(0, a_p[i]) + a_doff[i], a_src[i]);
#pragma unroll
    for (int i = 0; i < 2; i++) cp16(smb + WH_B(0, b_p[i]) + b_doff[i], b_src[i]);
    cp_commit();

    float acc[8][4];
#pragma unroll
    for (int j = 0; j < 8; j++)
#pragma unroll
        for (int q = 0; q < 4; q++) acc[j][q] = 0.f;

    const uint32_t aRow = (16 * wid + (lane & 15)) * (ASTR * 2) + (lane >> 4) * 16;
    const uint32_t bRow = (lane & 7) * (BSTR * 2) + (lane >> 3) * 16;

    for (int c = 0; c < NCH_W; c++) {
        const int p = c & 1, pn = p ^ 1;
        cp_wait<0>();
        __syncthreads();
        if (c + 1 < NCH_W) {
            const int kb = (c + 1) * KC;
#pragma unroll
            for (int i = 0; i < 4; i++) cp16(smb + WH_A(pn, a_p[i]) + a_doff[i], a_src[i] + kb);
#pragma unroll
            for (int i = 0; i < 2; i++) cp16(smb + WH_B(pn, b_p[i]) + b_doff[i], b_src[i] + kb);
            cp_commit();
        }
        uint32_t afh[2][4], afl[2][4];
        ldm4(afh[0], smb + WH_A(p, 0) + aRow);
        ldm4(afh[1], smb + WH_A(p, 0) + aRow + 32);
        ldm4(afl[0], smb + WH_A(p, 1) + aRow);
        ldm4(afl[1], smb + WH_A(p, 1) + aRow + 32);
#pragma unroll
        for (int j = 0; j < 8; j++) {
            uint32_t bh[4], bl[4];
            ldm4(bh, smb + WH_B(p, 0) + j * 8 * (BSTR * 2) + bRow);
            ldm4(bl, smb + WH_B(p, 1) + j * 8 * (BSTR * 2) + bRow);
            mma_bf16(acc[j], afh[0], bh[0], bh[1]);
            mma_bf16(acc[j], afh[0], bl[0], bl[1]);
            mma_bf16(acc[j], afl[0], bh[0], bh[1]);
            mma_bf16(acc[j], afh[1], bh[2], bh[3]);
            mma_bf16(acc[j], afh[1], bl[2], bl[3]);
            mma_bf16(acc[j], afl[1], bh[2], bh[3]);
        }
    }

    const int g = lane >> 2;
    const int row0 = nbase + 16 * wid + g;
    float* o0 = g_Wh + ((size_t)h * N_NODES + row0) * OUT_F + (lane & 3) * 2;
    float* o1 = o0 + 8 * OUT_F;
#pragma unroll
    for (int j = 0; j < 8; j++) {
        *(float2*)(o0 + j * 8) = make_float2(acc[j][0], acc[j][1]);
        *(float2*)(o1 + j * 8) = make_float2(acc[j][2], acc[j][3]);
    }
}

// ---------------- kernel: f1/f2 + unshifted exp tables ----------------
__global__ void attn_vec_kernel(const float* __restrict__ a1,
                                const float* __restrict__ a2) {
    int gw = (blockIdx.x * blockDim.x + threadIdx.x) >> 5;
    int lane = threadIdx.x & 31;
    if (gw >= HEADS * N_NODES) return;
    int h = gw >> 12;
    int n = gw & (N_NODES - 1);
    const float* whp = &g_Wh[(h * N_NODES + n) * OUT_F];
    float w0 = whp[lane], w1 = whp[lane + 32];
    float s1 = w0 * a1[h * OUT_F + lane] + w1 * a1[h * OUT_F + lane + 32];
    float s2 = w0 * a2[h * OUT_F + lane] + w1 * a2[h * OUT_F + lane + 32];
#pragma unroll
    for (int off = 16; off; off >>= 1) {
        s1 += __shfl_xor_sync(0xffffffffu, s1, off);
        s2 += __shfl_xor_sync(0xffffffffu, s2, off);
    }
    if (lane == 0) {
        int idx = h * N_NODES + n;
        g_f1[idx] = s1;
        g_f2[idx] = s2;
        g_P2[idx] = expf(s2);
        g_Q2[idx] = expf(ALPHA * s2);
    }
}

// ---------------- kernel: per-head max of f2 ----------------
__global__ __launch_bounds__(256) void maxf2_kernel() {
    __shared__ float red[256];
    const int h = blockIdx.x, t = threadIdx.x;
    float m = -3.4e38f;
#pragma unroll
    for (int i = 0; i < 16; i++) m = fmaxf(m, g_f2[h * N_NODES + t + i * 256]);
    red[t] = m;
    __syncthreads();
    for (int s = 128; s; s >>= 1) {
        if (t < s) red[t] = fmaxf(red[t], red[t + s]);
        __syncthreads();
    }
    if (t == 0) g_mx[h] = red[0];
}

// ---------------- kernel: shifted P1/Q1 ----------------
__global__ __launch_bounds__(256) void exp1_kernel() {
    int idx = blockIdx.x * blockDim.x + threadIdx.x;
    int h = idx >> 12;
    float f1 = g_f1[idx];
    float s = f1 + g_mx[h];
    float M = s > 0.f ? s : ALPHA * s;
    g_P1[idx] = expf(f1 - M);
    g_Q1[idx] = expf(ALPHA * f1 - M);
}

// ---------------- kernel: transpose + fp16 convert of Wh ----------------
__global__ __launch_bounds__(256) void whT_split_kernel() {
    __shared__ float T[64 * 65];
    const int h = blockIdx.y;
    const int mb = blockIdx.x * 64;
    const int t = threadIdx.x;
    const float* src = g_Wh + ((size_t)h * N_NODES + mb) * OUT_F;
#pragma unroll
    for (int i = 0; i < 16; i++) {
        int lin = t + i * 256;
        int m = lin >> 6, o = lin & 63;
        T[m * 65 + o] = src[lin];
    }
    __syncthreads();
#pragma unroll
    for (int i = 0; i < 8; i++) {
        int lin = t + i * 256;
        int o = lin >> 5, mp = lin & 31;
        __half2 h2 = __floats2half2_rn(T[(2 * mp) * 65 + o], T[(2 * mp + 1) * 65 + o]);
        size_t dst = ((size_t)h * OUT_F + o) * N_NODES + mb + 2 * mp;
        *reinterpret_cast<unsigned*>(&g_WhT_h16[dst]) = *reinterpret_cast<unsigned*>(&h2);
    }
}

// ---------------- kernel: fp16 HMMA fused masked-softmax aggregation ----------------
// 128 rows x 64 cols per CTA, 512 threads / 16 warps, warp tile 16x32.
__global__ __launch_bounds__(512, 2) void gat_mma_kernel(float* __restrict__ out) {
    extern __shared__ __align__(16) char sm[];
    const int t = threadIdx.x;
    const int wid = t >> 5, lane = t & 31;
    const int h = blockIdx.y;
    const int nbase = blockIdx.x * GAT_RT;
    const int hN = h * N_NODES;
    const uint32_t smb = smem_u32(sm);

    // w-gen assignment: row rr (0..127), quarter q -> 16 m's
    const int rr = t >> 2;
    const int q = t & 3;
    const int grow = nbase + rr;
    const float F1r = g_f1[hN + grow];
    const float P1r = g_P1[hN + grow];
    const float Q1r = g_Q1[hN + grow];
    const unsigned* adjrow = g_adjbits + (size_t)grow * (N_NODES / 32);
    float Dacc = 0.f;

    const __half* whTh = g_WhT_h16 + ((size_t)h * OUT_F) * N_NODES;

    // B staging: 512 quads ([64 o][8 quads]), 1 per thread
    const int br = t >> 3, bq = t & 7;
    const __half* b_src = whTh + (size_t)br * N_NODES + bq * 8;
    const uint32_t b_doff = (uint32_t)(br * (AST2 * 2) + bq * 16);

    // table staging: chunk cn -> GA_T(cn % 3); 48 quads, threads 0..47
    auto stageT = [&](int cn) {
        if (t < 48) {
            int tb = cn % 3;
            int table = t >> 4, q4 = t & 15;
            const float* base = (table == 0) ? g_f2 : ((table == 1) ? g_P2 : g_Q2);
            cp16(smb + GA_T(tb) + table * 256 + q4 * 16, base + hN + cn * KC2 + q4 * 4);
        }
    };

    // w-gen from SMEM tables -> A buffer `buf` (16 fp16 weights per thread)
    auto wgen = [&](int buf, int tb, unsigned awfull) {
        const float* Tf = (const float*)(sm + GA_T(tb));
        const unsigned aw = awfull >> ((q & 1) * 16);
        const uint32_t dst = smb + GA_A(buf) + rr * (AST2 * 2) + q * 32;
#pragma unroll
        for (int g4 = 0; g4 < 2; g4++) {
            float fv[8], pv[8], qv[8];
            *(float4*)&fv[0] = *(const float4*)&Tf[q * 16 + g4 * 8];
            *(float4*)&fv[4] = *(const float4*)&Tf[q * 16 + g4 * 8 + 4];
            *(float4*)&pv[0] = *(const float4*)&Tf[64 + q * 16 + g4 * 8];
            *(float4*)&pv[4] = *(const float4*)&Tf[64 + q * 16 + g4 * 8 + 4];
            *(float4*)&qv[0] = *(const float4*)&Tf[128 + q * 16 + g4 * 8];
            *(float4*)&qv[4] = *(const float4*)&Tf[128 + q * 16 + g4 * 8 + 4];
            float wv[8];
            float ds = 0.f;
#pragma unroll
            for (int e = 0; e < 8; e++) {
                int bit = g4 * 8 + e;
                float pos = F1r + fv[e];
                float w = (pos > 0.f) ? (P1r * pv[e]) : (Q1r * qv[e]);
                w = ((aw >> bit) & 1u) ? w : 0.f;
                ds += w;
                wv[e] = w;
            }
            Dacc += ds;
            unsigned hp[4];
#pragma unroll
            for (int e = 0; e < 4; e++) {
                __half2 h2 = __floats2half2_rn(wv[2 * e], wv[2 * e + 1]);
                hp[e] = *reinterpret_cast<unsigned*>(&h2);
            }
            asm volatile("st.shared.v4.b32 [%0], {%1, %2, %3, %4};"
                         :: "r"(dst + g4 * 16), "r"(hp[0]), "r"(hp[1]), "r"(hp[2]),
                            "r"(hp[3]) : "memory");
        }
    };

    // ---- prologue: B(0), T(0), T(1); then wgen(0) ----
    cp16(smb + GA_B(0) + b_doff, b_src);
    stageT(0);
    stageT(1);
    cp_commit();
    cp_wait<0>();
    __syncthreads();
    {
        unsigned aw0 = adjrow[q >> 1];
        wgen(0, 0, aw0);
    }

    float acc[4][4];
#pragma unroll
    for (int j = 0; j < 4; j++)
#pragma unroll
        for (int e = 0; e < 4; e++) acc[j][e] = 0.f;

    const int rgrp = wid & 7;        // 16-row group
    const int chalf = wid >> 3;      // 32-col half
    const uint32_t aRow = (16 * rgrp + (lane & 15)) * (AST2 * 2) + (lane >> 4) * 16;
    const int jbase = chalf * 32;    // output-column base
    const uint32_t bOff = (jbase + (lane & 7)) * (AST2 * 2) + (lane >> 3) * 16;

    for (int c = 0; c < NCH2; c++) {
        const int p = c & 1, pn = p ^ 1;
        // wait: completes group from previous iteration = {B(c), T(c+1)}
        cp_wait<0>();
        __syncthreads();

        unsigned aw_next = 0;
        if (c + 1 < NCH2) {
            aw_next = adjrow[(c + 1) * 2 + (q >> 1)];
            cp16(smb + GA_B(pn) + b_doff, b_src + (c + 1) * KC2);
            if (c + 2 < NCH2) stageT(c + 2);
            cp_commit();
        }

        // MMA on buffer p
        uint32_t af[4][4];
#pragma unroll
        for (int s = 0; s < 4; s++) ldm4(af[s], smb + GA_A(p) + aRow + s * 32);
#pragma unroll
        for (int j = 0; j < 4; j++) {
            uint32_t b0[4], b1[4];
            const uint32_t bj = smb + GA_B(p) + j * 8 * (AST2 * 2) + bOff;
            ldm4(b0, bj);
            ldm4(b1, bj + 64);
            mma_f16(acc[j], af[0], b0[0], b0[1]);
            mma_f16(acc[j], af[1], b0[2], b0[3]);
            mma_f16(acc[j], af[2], b1[0], b1[1]);
            mma_f16(acc[j], af[3], b1[2], b1[3]);
        }

        // w-gen for next chunk into other A buffer (tables already in SMEM)
        if (c + 1 < NCH2) wgen(pn, (c + 1) % 3, aw_next);
    }

    float* Dsh = (float*)(sm + GA_DSH);
    Dsh[t] = Dacc;
    __syncthreads();

    const int g = lane >> 2;
    const int row0 = 16 * rgrp + g;
    const int row1 = row0 + 8;
    const float inv0 =
        1.0f / (Dsh[4 * row0] + Dsh[4 * row0 + 1] + Dsh[4 * row0 + 2] + Dsh[4 * row0 + 3]);
    const float inv1 =
        1.0f / (Dsh[4 * row1] + Dsh[4 * row1 + 1] + Dsh[4 * row1 + 2] + Dsh[4 * row1 + 3]);
    float* o0 = out + (size_t)(nbase + row0) * (HEADS * OUT_F) + h * OUT_F + jbase +
                (lane & 3) * 2;
    float* o1 = out + (size_t)(nbase + row1) * (HEADS * OUT_F) + h * OUT_F + jbase +
                (lane & 3) * 2;
#pragma unroll
    for (int j = 0; j < 4; j++) {
        *(float2*)(o0 + j * 8) = make_float2(acc[j][0] * inv0, acc[j][1] * inv0);
        *(float2*)(o1 + j * 8) = make_float2(acc[j][2] * inv1, acc[j][3] * inv1);
    }
}

// ---------------- launch ----------------
extern "C" void kernel_launch(void* const* d_in, const int* in_sizes, int n_in,
                              void* d_out, int out_size) {
    const float* x   = (const float*)d_in[0];
    const int*   adj = (const int*)d_in[1];
    const float* W   = (const float*)d_in[2];
    const float* a1  = (const float*)d_in[3];
    const float* a2  = (const float*)d_in[4];
    float* out = (float*)d_out;

    cudaFuncSetAttribute(wh_mma_kernel, cudaFuncAttributeMaxDynamicSharedMemorySize,
                         WH_SMEM);
    cudaFuncSetAttribute(gat_mma_kernel, cudaFuncAttributeMaxDynamicSharedMemorySize,
                         GA_SMEM);

    bitpack_kernel<<<(N_NODES * N_NODES / 32) / 256, 256>>>(adj);
    xsplit_kernel<<<(N_NODES * IN_F) / (256 * 8), 256>>>(x);
    wsplit_kernel<<<HEADS, 256>>>(W);

    dim3 gW(N_NODES / RT, HEADS);
    wh_mma_kernel<<<gW, 256, WH_SMEM>>>();

    attn_vec_kernel<<<(HEADS * N_NODES * 32) / 256, 256>>>(a1, a2);
    maxf2_kernel<<<HEADS, 256>>>();
    exp1_kernel<<<(HEADS * N_NODES) / 256, 256>>>();

    dim3 gT(N_NODES / 64, HEADS);
    whT_split_kernel<<<gT, 256>>>();

    dim3 gD(N_NODES / GAT_RT, HEADS);
    gat_mma_kernel<<<gD, 512, GA_SMEM>>>(out);
}

// round 11
// speedup vs baseline: 1.1191x; 1.0416x over previous
#include <cuda_runtime.h>
#include <cuda_bf16.h>
#include <cuda_fp16.h>
#include <cstdint>

#define N_NODES 4096
#define IN_F 512
#define OUT_F 64
#define HEADS 8
#define ALPHA 0.2f

#define RT 128                 // rows per CTA (wh kernel)
#define KC 32                  // k per chunk (wh kernel)
#define NCH_W (IN_F / KC)      // 16 chunks (wh)
#define ASTR 40                // padded bf16 row stride (80 B) (wh kernel)
#define BSTR 40

// ---- wh dynamic smem offsets ----
#define WH_A(buf, prec) ((buf) * 20480 + (prec) * 10240)
#define WH_B(buf, prec) (40960 + (buf) * 10240 + (prec) * 5120)
#define WH_T 0                  // epilogue transpose tile [64][136] fp16 (17408 B)
#define WH_AV 18432             // epilogue a1/a2 staging (128 floats)
#define WH_SMEM 61440

// ---- gat (fp16, 128x64 tile, 512 threads, KC2=64, smem tables) ----
#define GAT_RT 128
#define KC2 64
#define NCH2 (N_NODES / KC2)   // 64 chunks
#define AST2 72                // fp16 stride (144 B)
#define GA_A(buf) ((buf) * 18432)           // [128][72] fp16, 2 bufs
#define GA_B(buf) (36864 + (buf) * 9216)    // [64][72] fp16, 2 bufs
#define GA_T(tb)  (55296 + (tb) * 768)      // [3 tables][64] float, 3 bufs
#define GA_DSH 57600                        // 512 floats
#define GA_SMEM 59904

// ---------------- scratch (device globals; no allocation) ----------------
__device__ __align__(16) float g_Wh[HEADS * N_NODES * OUT_F];          // 8 MB [h][n][o]
__device__ float g_f1[HEADS * N_NODES];
__device__ float g_f2[HEADS * N_NODES];
__device__ float g_P1[HEADS * N_NODES];   // exp(f1 - M)  (shifted)
__device__ float g_P2[HEADS * N_NODES];   // exp(f2)
__device__ float g_Q1[HEADS * N_NODES];   // exp(a*f1 - M)
__device__ float g_Q2[HEADS * N_NODES];   // exp(a*f2)
__device__ float g_mx[HEADS];             // per-head max f2
__device__ unsigned g_adjbits[N_NODES * (N_NODES / 32)];               // 2 MB
__device__ __align__(16) __half g_WhT_h16[HEADS * OUT_F * N_NODES];    // 4 MB [h][o][m]
__device__ __align__(16) __nv_bfloat16 g_x_hi[N_NODES * IN_F];         // 4 MB [n][k]
__device__ __align__(16) __nv_bfloat16 g_x_lo[N_NODES * IN_F];
__device__ __align__(16) __nv_bfloat16 g_WT_hi[HEADS * OUT_F * IN_F];  // 512 KB [h][o][k]
__device__ __align__(16) __nv_bfloat16 g_WT_lo[HEADS * OUT_F * IN_F];

// ---------------- helpers ----------------
__device__ __forceinline__ uint32_t smem_u32(const void* p) {
    uint32_t a;
    asm("{ .reg .u64 t; cvta.to.shared.u64 t, %1; cvt.u32.u64 %0, t; }" : "=r"(a) : "l"(p));
    return a;
}
__device__ __forceinline__ void cp16(uint32_t dst, const void* src) {
    asm volatile("cp.async.cg.shared.global [%0], [%1], 16;" :: "r"(dst), "l"(src) : "memory");
}
__device__ __forceinline__ void cp_commit() {
    asm volatile("cp.async.commit_group;" ::: "memory");
}
template <int N>
__device__ __forceinline__ void cp_wait() {
    asm volatile("cp.async.wait_group %0;" :: "n"(N) : "memory");
}
__device__ __forceinline__ void ldm4(uint32_t* r, uint32_t addr) {
    asm volatile("ldmatrix.sync.aligned.m8n8.x4.shared.b16 {%0,%1,%2,%3}, [%4];"
                 : "=r"(r[0]), "=r"(r[1]), "=r"(r[2]), "=r"(r[3]) : "r"(addr) : "memory");
}
__device__ __forceinline__ void mma_bf16(float* c, const uint32_t* a, uint32_t b0,
                                         uint32_t b1) {
    asm("mma.sync.aligned.m16n8k16.row.col.f32.bf16.bf16.f32 "
        "{%0,%1,%2,%3}, {%4,%5,%6,%7}, {%8,%9}, {%0,%1,%2,%3};"
        : "+f"(c[0]), "+f"(c[1]), "+f"(c[2]), "+f"(c[3])
        : "r"(a[0]), "r"(a[1]), "r"(a[2]), "r"(a[3]), "r"(b0), "r"(b1));
}
__device__ __forceinline__ void mma_f16(float* c, const uint32_t* a, uint32_t b0,
                                        uint32_t b1) {
    asm("mma.sync.aligned.m16n8k16.row.col.f32.f16.f16.f32 "
        "{%0,%1,%2,%3}, {%4,%5,%6,%7}, {%8,%9}, {%0,%1,%2,%3};"
        : "+f"(c[0]), "+f"(c[1]), "+f"(c[2]), "+f"(c[3])
        : "r"(a[0]), "r"(a[1]), "r"(a[2]), "r"(a[3]), "r"(b0), "r"(b1));
}
__device__ __forceinline__ void split_pair(float x, float y, unsigned& hi, unsigned& lo) {
    __nv_bfloat162 h2 = __float22bfloat162_rn(make_float2(x, y));
    float2 hf = __bfloat1622float2(h2);
    __nv_bfloat162 l2 = __float22bfloat162_rn(make_float2(x - hf.x, y - hf.y));
    hi = *reinterpret_cast<unsigned*>(&h2);
    lo = *reinterpret_cast<unsigned*>(&l2);
}

// ---------------- kernel: fused prep (bitpack | xsplit | wsplit) ----------------
__global__ __launch_bounds__(256) void prep_kernel(const int* __restrict__ adj,
                                                   const float* __restrict__ x,
                                                   const float* __restrict__ W) {
    const int b = blockIdx.x;
    const int tid = threadIdx.x;
    if (b < 2048) {
        // bitpack: 32 adj entries per thread
        int t = b * 256 + tid;
        const int4* p = (const int4*)adj + (size_t)t * 8;
        unsigned w = 0;
#pragma unroll
        for (int i = 0; i < 8; i++) {
            int4 v = p[i];
            w |= (v.x > 0 ? 1u : 0u) << (4 * i);
            w |= (v.y > 0 ? 1u : 0u) << (4 * i + 1);
            w |= (v.z > 0 ? 1u : 0u) << (4 * i + 2);
            w |= (v.w > 0 ? 1u : 0u) << (4 * i + 3);
        }
        g_adjbits[t] = w;
    } else if (b < 3072) {
        // xsplit: 8 floats per thread
        int gid = (b - 2048) * 256 + tid;
        const float4* xp = (const float4*)x + gid * 2;
        float4 v0 = xp[0], v1 = xp[1];
        float f[8] = {v0.x, v0.y, v0.z, v0.w, v1.x, v1.y, v1.z, v1.w};
        unsigned hw[4], lw[4];
#pragma unroll
        for (int i = 0; i < 4; i++) split_pair(f[2 * i], f[2 * i + 1], hw[i], lw[i]);
        *(uint4*)(g_x_hi + (size_t)gid * 8) = make_uint4(hw[0], hw[1], hw[2], hw[3]);
        *(uint4*)(g_x_lo + (size_t)gid * 8) = make_uint4(lw[0], lw[1], lw[2], lw[3]);
    } else {
        // wsplit: one head per block
        const int h = b - 3072;
#pragma unroll 4
        for (int i = 0; i < 128; i++) {
            int lin = i * 256 + tid;
            int o = lin >> 9, k = lin & 511;
            float v = W[((size_t)h * IN_F + k) * OUT_F + o];
            __nv_bfloat16 hb = __float2bfloat16(v);
            __nv_bfloat16 lb = __float2bfloat16(v - __bfloat162float(hb));
            size_t d = ((size_t)h * OUT_F + o) * IN_F + k;
            g_WT_hi[d] = hb;
            g_WT_lo[d] = lb;
        }
    }
}

// ---------------- kernel: Wh = x @ W via HMMA + fused f1/f2/exp/WhT epilogue ----------------
__global__ __launch_bounds__(256, 2) void wh_mma_kernel(const float* __restrict__ a1v,
                                                        const float* __restrict__ a2v) {
    extern __shared__ __align__(16) char sm[];
    const int t = threadIdx.x;
    const int wid = t >> 5, lane = t & 31;
    const int h = blockIdx.y;
    const int nbase = blockIdx.x * RT;

    const int a_p[4] = {(t * 4) >> 9, (t * 4 + 1) >> 9, (t * 4 + 2) >> 9, (t * 4 + 3) >> 9};
    int a_r[4], a_q[4];
    const __nv_bfloat16* a_src[4];
    uint32_t a_doff[4];
#pragma unroll
    for (int i = 0; i < 4; i++) {
        int idx = t * 4 + i;
        a_r[i] = (idx >> 2) & 127;
        a_q[i] = idx & 3;
        a_src[i] = (a_p[i] ? g_x_lo : g_x_hi) + (size_t)(nbase + a_r[i]) * IN_F + a_q[i] * 8;
        a_doff[i] = (uint32_t)(a_r[i] * (ASTR * 2) + a_q[i] * 16);
    }
    int b_p[2];
    const __nv_bfloat16* b_src[2];
    uint32_t b_doff[2];
#pragma unroll
    for (int i = 0; i < 2; i++) {
        int idx = t * 2 + i;
        b_p[i] = idx >> 8;
        int br = (idx >> 2) & 63, bq = idx & 3;
        b_src[i] = (b_p[i] ? g_WT_lo : g_WT_hi) + ((size_t)h * OUT_F + br) * IN_F + bq * 8;
        b_doff[i] = (uint32_t)(br * (BSTR * 2) + bq * 16);
    }
    const uint32_t smb = smem_u32(sm);

#pragma unroll
    for (int i = 0; i < 4; i++) cp16(smb + WH_A(0, a_p[i]) + a_doff[i], a_src[i]);
#pragma unroll
    for (int i = 0; i < 2; i++) cp16(smb + WH_B(0, b_p[i]) + b_doff[i], b_src[i]);
    cp_commit();

    float acc[8][4];
#pragma unroll
    for (int j = 0; j < 8; j++)
#pragma unroll
        for (int q = 0; q < 4; q++) acc[j][q] = 0.f;

    const uint32_t aRow = (16 * wid + (lane & 15)) * (ASTR * 2) + (lane >> 4) * 16;
    const uint32_t bRow = (lane & 7) * (BSTR * 2) + (lane >> 3) * 16;

    for (int c = 0; c < NCH_W; c++) {
        const int p = c & 1, pn = p ^ 1;
        cp_wait<0>();
        __syncthreads();
        if (c + 1 < NCH_W) {
            const int kb = (c + 1) * KC;
#pragma unroll
            for (int i = 0; i < 4; i++) cp16(smb + WH_A(pn, a_p[i]) + a_doff[i], a_src[i] + kb);
#pragma unroll
            for (int i = 0; i < 2; i++) cp16(smb + WH_B(pn, b_p[i]) + b_doff[i], b_src[i] + kb);
            cp_commit();
        }
        uint32_t afh[2][4], afl[2][4];
        ldm4(afh[0], smb + WH_A(p, 0) + aRow);
        ldm4(afh[1], smb + WH_A(p, 0) + aRow + 32);
        ldm4(afl[0], smb + WH_A(p, 1) + aRow);
        ldm4(afl[1], smb + WH_A(p, 1) + aRow + 32);
#pragma unroll
        for (int j = 0; j < 8; j++) {
            uint32_t bh[4], bl[4];
            ldm4(bh, smb + WH_B(p, 0) + j * 8 * (BSTR * 2) + bRow);
            ldm4(bl, smb + WH_B(p, 1) + j * 8 * (BSTR * 2) + bRow);
            mma_bf16(acc[j], afh[0], bh[0], bh[1]);
            mma_bf16(acc[j], afh[0], bl[0], bl[1]);
            mma_bf16(acc[j], afl[0], bh[0], bh[1]);
            mma_bf16(acc[j], afh[1], bh[2], bh[3]);
            mma_bf16(acc[j], afh[1], bl[2], bl[3]);
            mma_bf16(acc[j], afl[1], bh[2], bh[3]);
        }
        __syncthreads();
    }

    // ---------- fused epilogue ----------
    const int g = lane >> 2;
    const int c2 = (lane & 3) * 2;          // column pair base
    const int row0 = nbase + 16 * wid + g;  // global row for acc[.][0..1]
    const int row1 = row0 + 8;              // global row for acc[.][2..3]

    // 1) write fp32 Wh
    float* o0 = g_Wh + ((size_t)h * N_NODES + row0) * OUT_F + c2;
    float* o1 = g_Wh + ((size_t)h * N_NODES + row1) * OUT_F + c2;
#pragma unroll
    for (int j = 0; j < 8; j++) {
        *(float2*)(o0 + j * 8) = make_float2(acc[j][0], acc[j][1]);
        *(float2*)(o1 + j * 8) = make_float2(acc[j][2], acc[j][3]);
    }

    // 2) stage transpose tile + a1/a2 vectors
    __half* T = (__half*)(sm + WH_T);       // [64][136] fp16
    float* av = (float*)(sm + WH_AV);       // a1[64], a2[64]
    if (t < 64) {
        av[t] = a1v[h * OUT_F + t];
        av[64 + t] = a2v[h * OUT_F + t];
    }
    const int ml0 = 16 * wid + g;           // CTA-local m for row0
#pragma unroll
    for (int j = 0; j < 8; j++) {
        int o = c2 + j * 8;
        T[o * 136 + ml0] = __float2half(acc[j][0]);
        T[(o + 1) * 136 + ml0] = __float2half(acc[j][1]);
        T[o * 136 + ml0 + 8] = __float2half(acc[j][2]);
        T[(o + 1) * 136 + ml0 + 8] = __float2half(acc[j][3]);
    }
    __syncthreads();

    // 3) write WhT fp16 (coalesced uint4)
#pragma unroll
    for (int i = 0; i < 4; i++) {
        int idx = t * 4 + i;                // 1024 uint4
        int o = idx >> 4, q = idx & 15;
        uint4 v = *(const uint4*)(T + o * 136 + q * 8);
        *(uint4*)(g_WhT_h16 + ((size_t)h * OUT_F + o) * N_NODES + nbase + q * 8) = v;
    }

    // 4) f1/f2 dots + exp tables
    float f10 = 0.f, f20 = 0.f, f11 = 0.f, f21 = 0.f;
#pragma unroll
    for (int j = 0; j < 8; j++) {
        int o = c2 + j * 8;
        float a1x = av[o], a1y = av[o + 1];
        float a2x = av[64 + o], a2y = av[64 + o + 1];
        f10 += acc[j][0] * a1x + acc[j][1] * a1y;
        f20 += acc[j][0] * a2x + acc[j][1] * a2y;
        f11 += acc[j][2] * a1x + acc[j][3] * a1y;
        f21 += acc[j][2] * a2x + acc[j][3] * a2y;
    }
#pragma unroll
    for (int off = 1; off <= 2; off <<= 1) {
        f10 += __shfl_xor_sync(0xffffffffu, f10, off);
        f20 += __shfl_xor_sync(0xffffffffu, f20, off);
        f11 += __shfl_xor_sync(0xffffffffu, f11, off);
        f21 += __shfl_xor_sync(0xffffffffu, f21, off);
    }
    if ((lane & 3) == 0) {
        int i0 = h * N_NODES + row0;
        int i1 = h * N_NODES + row1;
        g_f1[i0] = f10;
        g_f2[i0] = f20;
        g_P2[i0] = expf(f20);
        g_Q2[i0] = expf(ALPHA * f20);
        g_f1[i1] = f11;
        g_f2[i1] = f21;
        g_P2[i1] = expf(f21);
        g_Q2[i1] = expf(ALPHA * f21);
    }
}

// ---------------- kernel: per-head max of f2 ----------------
__global__ __launch_bounds__(256) void maxf2_kernel() {
    __shared__ float red[256];
    const int h = blockIdx.x, t = threadIdx.x;
    float m = -3.4e38f;
#pragma unroll
    for (int i = 0; i < 16; i++) m = fmaxf(m, g_f2[h * N_NODES + t + i * 256]);
    red[t] = m;
    __syncthreads();
    for (int s = 128; s; s >>= 1) {
        if (t < s) red[t] = fmaxf(red[t], red[t + s]);
        __syncthreads();
    }
    if (t == 0) g_mx[h] = red[0];
}

// ---------------- kernel: shifted P1/Q1 ----------------
__global__ __launch_bounds__(256) void exp1_kernel() {
    int idx = blockIdx.x * blockDim.x + threadIdx.x;
    int h = idx >> 12;
    float f1 = g_f1[idx];
    float s = f1 + g_mx[h];
    float M = s > 0.f ? s : ALPHA * s;
    g_P1[idx] = expf(f1 - M);
    g_Q1[idx] = expf(ALPHA * f1 - M);
}

// ---------------- kernel: fp16 HMMA fused masked-softmax aggregation ----------------
// 128 rows x 64 cols per CTA, 512 threads / 16 warps, warp tile 16x32. (unchanged)
__global__ __launch_bounds__(512, 2) void gat_mma_kernel(float* __restrict__ out) {
    extern __shared__ __align__(16) char sm[];
    const int t = threadIdx.x;
    const int wid = t >> 5, lane = t & 31;
    const int h = blockIdx.y;
    const int nbase = blockIdx.x * GAT_RT;
    const int hN = h * N_NODES;
    const uint32_t smb = smem_u32(sm);

    const int rr = t >> 2;
    const int q = t & 3;
    const int grow = nbase + rr;
    const float F1r = g_f1[hN + grow];
    const float P1r = g_P1[hN + grow];
    const float Q1r = g_Q1[hN + grow];
    const unsigned* adjrow = g_adjbits + (size_t)grow * (N_NODES / 32);
    float Dacc = 0.f;

    const __half* whTh = g_WhT_h16 + ((size_t)h * OUT_F) * N_NODES;

    const int br = t >> 3, bq = t & 7;
    const __half* b_src = whTh + (size_t)br * N_NODES + bq * 8;
    const uint32_t b_doff = (uint32_t)(br * (AST2 * 2) + bq * 16);

    auto stageT = [&](int cn) {
        if (t < 48) {
            int tb = cn % 3;
            int table = t >> 4, q4 = t & 15;
            const float* base = (table == 0) ? g_f2 : ((table == 1) ? g_P2 : g_Q2);
            cp16(smb + GA_T(tb) + table * 256 + q4 * 16, base + hN + cn * KC2 + q4 * 4);
        }
    };

    auto wgen = [&](int buf, int tb, unsigned awfull) {
        const float* Tf = (const float*)(sm + GA_T(tb));
        const unsigned aw = awfull >> ((q & 1) * 16);
        const uint32_t dst = smb + GA_A(buf) + rr * (AST2 * 2) + q * 32;
#pragma unroll
        for (int g4 = 0; g4 < 2; g4++) {
            float fv[8], pv[8], qv[8];
            *(float4*)&fv[0] = *(const float4*)&Tf[q * 16 + g4 * 8];
            *(float4*)&fv[4] = *(const float4*)&Tf[q * 16 + g4 * 8 + 4];
            *(float4*)&pv[0] = *(const float4*)&Tf[64 + q * 16 + g4 * 8];
            *(float4*)&pv[4] = *(const float4*)&Tf[64 + q * 16 + g4 * 8 + 4];
            *(float4*)&qv[0] = *(const float4*)&Tf[128 + q * 16 + g4 * 8];
            *(float4*)&qv[4] = *(const float4*)&Tf[128 + q * 16 + g4 * 8 + 4];
            float wv[8];
            float ds = 0.f;
#pragma unroll
            for (int e = 0; e < 8; e++) {
                int bit = g4 * 8 + e;
                float pos = F1r + fv[e];
                float w = (pos > 0.f) ? (P1r * pv[e]) : (Q1r * qv[e]);
                w = ((aw >> bit) & 1u) ? w : 0.f;
                ds += w;
                wv[e] = w;
            }
            Dacc += ds;
            unsigned hp[4];
#pragma unroll
            for (int e = 0; e < 4; e++) {
                __half2 h2 = __floats2half2_rn(wv[2 * e], wv[2 * e + 1]);
                hp[e] = *reinterpret_cast<unsigned*>(&h2);
            }
            asm volatile("st.shared.v4.b32 [%0], {%1, %2, %3, %4};"
                         :: "r"(dst + g4 * 16), "r"(hp[0]), "r"(hp[1]), "r"(hp[2]),
                            "r"(hp[3]) : "memory");
        }
    };

    cp16(smb + GA_B(0) + b_doff, b_src);
    stageT(0);
    stageT(1);
    cp_commit();
    cp_wait<0>();
    __syncthreads();
    {
        unsigned aw0 = adjrow[q >> 1];
        wgen(0, 0, aw0);
    }

    float acc[4][4];
#pragma unroll
    for (int j = 0; j < 4; j++)
#pragma unroll
        for (int e = 0; e < 4; e++) acc[j][e] = 0.f;

    const int rgrp = wid & 7;
    const int chalf = wid >> 3;
    const uint32_t aRow = (16 * rgrp + (lane & 15)) * (AST2 * 2) + (lane >> 4) * 16;
    const int jbase = chalf * 32;
    const uint32_t bOff = (jbase + (lane & 7)) * (AST2 * 2) + (lane >> 3) * 16;

    for (int c = 0; c < NCH2; c++) {
        const int p = c & 1, pn = p ^ 1;
        cp_wait<0>();
        __syncthreads();

        unsigned aw_next = 0;
        if (c + 1 < NCH2) {
            aw_next = adjrow[(c + 1) * 2 + (q >> 1)];
            cp16(smb + GA_B(pn) + b_doff, b_src + (c + 1) * KC2);
            if (c + 2 < NCH2) stageT(c + 2);
            cp_commit();
        }

        uint32_t af[4][4];
#pragma unroll
        for (int s = 0; s < 4; s++) ldm4(af[s], smb + GA_A(p) + aRow + s * 32);
#pragma unroll
        for (int j = 0; j < 4; j++) {
            uint32_t b0[4], b1[4];
            const uint32_t bj = smb + GA_B(p) + j * 8 * (AST2 * 2) + bOff;
            ldm4(b0, bj);
            ldm4(b1, bj + 64);
            mma_f16(acc[j], af[0], b0[0], b0[1]);
            mma_f16(acc[j], af[1], b0[2], b0[3]);
            mma_f16(acc[j], af[2], b1[0], b1[1]);
            mma_f16(acc[j], af[3], b1[2], b1[3]);
        }

        if (c + 1 < NCH2) wgen(pn, (c + 1) % 3, aw_next);
    }

    float* Dsh = (float*)(sm + GA_DSH);
    Dsh[t] = Dacc;
    __syncthreads();

    const int g = lane >> 2;
    const int row0 = 16 * rgrp + g;
    const int row1 = row0 + 8;
    const float inv0 =
        1.0f / (Dsh[4 * row0] + Dsh[4 * row0 + 1] + Dsh[4 * row0 + 2] + Dsh[4 * row0 + 3]);
    const float inv1 =
        1.0f / (Dsh[4 * row1] + Dsh[4 * row1 + 1] + Dsh[4 * row1 + 2] + Dsh[4 * row1 + 3]);
    float* o0 = out + (size_t)(nbase + row0) * (HEADS * OUT_F) + h * OUT_F + jbase +
                (lane & 3) * 2;
    float* o1 = out + (size_t)(nbase + row1) * (HEADS * OUT_F) + h * OUT_F + jbase +
                (lane & 3) * 2;
#pragma unroll
    for (int j = 0; j < 4; j++) {
        *(float2*)(o0 + j * 8) = make_float2(acc[j][0] * inv0, acc[j][1] * inv0);
        *(float2*)(o1 + j * 8) = make_float2(acc[j][2] * inv1, acc[j][3] * inv1);
    }
}

// ---------------- launch ----------------
extern "C" void kernel_launch(void* const* d_in, const int* in_sizes, int n_in,
                              void* d_out, int out_size) {
    const float* x   = (const float*)d_in[0];
    const int*   adj = (const int*)d_in[1];
    const float* W   = (const float*)d_in[2];
    const float* a1  = (const float*)d_in[3];
    const float* a2  = (const float*)d_in[4];
    float* out = (float*)d_out;

    cudaFuncSetAttribute(wh_mma_kernel, cudaFuncAttributeMaxDynamicSharedMemorySize,
                         WH_SMEM);
    cudaFuncSetAttribute(gat_mma_kernel, cudaFuncAttributeMaxDynamicSharedMemorySize,
                         GA_SMEM);

    prep_kernel<<<3080, 256>>>(adj, x, W);

    dim3 gW(N_NODES / RT, HEADS);
    wh_mma_kernel<<<gW, 256, WH_SMEM>>>(a1, a2);

    maxf2_kernel<<<HEADS, 256>>>();
    exp1_kernel<<<(HEADS * N_NODES) / 256, 256>>>();

    dim3 gD(N_NODES / GAT_RT, HEADS);
    gat_mma_kernel<<<gD, 512, GA_SMEM>>>(out);
}